// round 12
// baseline (speedup 1.0000x reference)
#include <cuda_runtime.h>
#include <cuda_bf16.h>
#include <math.h>

#define Bn 64
#define Ln 256
#define En 300
#define Mn 50
#define Dn 350
#define HDn 128
#define Gn 512   // 4*HD
#define Hn 256
#define KPAD 384

typedef unsigned long long ull;

// Scratch (device globals; no allocation allowed)
__device__ float g_gates_f[Bn*Ln*Gn];
__device__ float g_gates_b[Bn*Ln*Gn];
__device__ float g_hf[Bn*Ln*HDn];
__device__ float g_hb[Bn*Ln*HDn];
// GEMM bf16 hi/lo operand scratch
__device__ __nv_bfloat16 g_A_hi[(size_t)Bn*Ln*KPAD];
__device__ __nv_bfloat16 g_A_lo[(size_t)Bn*Ln*KPAD];
__device__ __nv_bfloat16 g_B_hi[2*Gn*KPAD];
__device__ __nv_bfloat16 g_B_lo[2*Gn*KPAD];
// LSTM weights, thread-mapped for split-k 512-thread layout
#define KRQ 11
#define KSQ 5
__device__ ulonglong2 g_wrA[2*KRQ*512];
__device__ ulonglong2 g_wrB[2*KRQ*512];
__device__ ulonglong2 g_wsA[2*KSQ*512];
__device__ ulonglong2 g_wsB[2*KSQ*512];
__device__ float g_cls[Bn];
__device__ float g_spsum[Bn];
__device__ unsigned g_crf_done;   // zero-init; self-resetting completion counter

// Fast activations: MUFU.TANH based
__device__ __forceinline__ float tanha(float x){
    float r; asm("tanh.approx.f32 %0, %1;" : "=f"(r) : "f"(x)); return r;
}
__device__ __forceinline__ float sigf(float x){
    return fmaf(tanha(0.5f*x), 0.5f, 0.5f);
}
__device__ __forceinline__ float lse2(float a, float b){
    float m = fmaxf(a,b);
    return m + __logf(__expf(a-m)+__expf(b-m));
}
__device__ __forceinline__ void ffma2(ull &d, ull a, ull b){
    asm("fma.rn.f32x2 %0, %1, %2, %0;" : "+l"(d) : "l"(a), "l"(b));
}
__device__ __forceinline__ ull addf2(ull a, ull b){
    ull r; asm("add.rn.f32x2 %0, %1, %2;" : "=l"(r) : "l"(a), "l"(b)); return r;
}
__device__ __forceinline__ ull pack2(float lo, float hi){
    ull r; asm("mov.b64 %0, {%1, %2};" : "=l"(r) : "r"(__float_as_uint(lo)), "r"(__float_as_uint(hi))); return r;
}
__device__ __forceinline__ float2 unpk(ull v){
    unsigned lo, hi; asm("mov.b64 {%0, %1}, %2;" : "=r"(lo), "=r"(hi) : "l"(v));
    return make_float2(__uint_as_float(lo), __uint_as_float(hi));
}
__device__ __forceinline__ void splitpack(float a, float b, unsigned &hw, unsigned &lw){
    __nv_bfloat16 ha = __float2bfloat16_rn(a);
    __nv_bfloat16 hb = __float2bfloat16_rn(b);
    __nv_bfloat16 la = __float2bfloat16_rn(a - __bfloat162float(ha));
    __nv_bfloat16 lb = __float2bfloat16_rn(b - __bfloat162float(hb));
    hw = ((unsigned)__bfloat16_as_ushort(hb) << 16) | (unsigned)__bfloat16_as_ushort(ha);
    lw = ((unsigned)__bfloat16_as_ushort(lb) << 16) | (unsigned)__bfloat16_as_ushort(la);
}
__device__ __forceinline__ void cpasync16(unsigned dst, const void* src){
    asm volatile("cp.async.cg.shared.global [%0], [%1], 16;" :: "r"(dst), "l"(src));
}
#define LDSM4(d0,d1,d2,d3,addr) \
    asm volatile("ldmatrix.sync.aligned.m8n8.x4.shared.b16 {%0,%1,%2,%3}, [%4];" \
        : "=r"(d0),"=r"(d1),"=r"(d2),"=r"(d3) : "r"(addr))
#define MMA_BF16(c,a,b0v,b1v) \
    asm volatile("mma.sync.aligned.m16n8k16.row.col.f32.bf16.bf16.f32 " \
        "{%0,%1,%2,%3}, {%4,%5,%6,%7}, {%8,%9}, {%0,%1,%2,%3};" \
        : "+f"(c[0]),"+f"(c[1]),"+f"(c[2]),"+f"(c[3]) \
        : "r"(a[0]),"r"(a[1]),"r"(a[2]),"r"(a[3]), "r"(b0v),"r"(b1v))

// ---------------------------------------------------------------------------
// Kernel 0: LSTM weight chunks for split-k layout.
// Thread mapping (t in [0,512)): w=t>>5, lane=t&31, gp=w*16+(lane&15),
// khalf=lane>>4; e=gp>>1, ghalf=gp&1, gA=ghalf*128+e, gB=gA+256.
// q = khalf*16 + j, j in [0,16): j<KRQ -> g_wr*[d][j][t], else g_ws*[d][j-KRQ][t]
// grid: (2 dirs * 16 j * 512 t) / 256 = 64 blocks
// ---------------------------------------------------------------------------
__global__ void prep_w_kernel(const float* __restrict__ w_f,
                              const float* __restrict__ w_b) {
    const int idx = blockIdx.x*256 + threadIdx.x;   // [0, 16384)
    const int d = idx >> 13;
    const int r = idx & 8191;
    const int j = r >> 9;         // [0,16)
    const int t = r & 511;
    const float* __restrict__ w = d ? w_b : w_f;
    const int wrp = t >> 5, lane = t & 31;
    const int gp = wrp*16 + (lane & 15);
    const int khalf = lane >> 4;
    const int e = gp >> 1, ghalf = gp & 1;
    const int gA = ghalf*128 + e;
    const int gB = gA + 256;
    const int q = khalf*16 + j;
    const float4 a = *(const float4*)&w[(size_t)gA*HDn + 4*q];
    const float4 b = *(const float4*)&w[(size_t)gB*HDn + 4*q];
    ulonglong2 ua, ub;
    ua.x = pack2(a.x, a.y); ua.y = pack2(a.z, a.w);
    ub.x = pack2(b.x, b.y); ub.y = pack2(b.z, b.w);
    if (j < KRQ) {
        g_wrA[((size_t)d*KRQ + j)*512 + t] = ua;
        g_wrB[((size_t)d*KRQ + j)*512 + t] = ub;
    } else {
        g_wsA[((size_t)d*KSQ + (j-KRQ))*512 + t] = ua;
        g_wsB[((size_t)d*KSQ + (j-KRQ))*512 + t] = ub;
    }
}

// ---------------------------------------------------------------------------
// Kernel 0b: build bf16 hi/lo GEMM operands.
// ---------------------------------------------------------------------------
__global__ void __launch_bounds__(256)
prep_ab_kernel(const int* __restrict__ sents, const int* __restrict__ masks,
               const float* __restrict__ we, const float* __restrict__ me,
               const float* __restrict__ w_ih_f, const float* __restrict__ w_ih_b) {
    const int bid = blockIdx.x;
    const int t = threadIdx.x;
    float v[8];
    size_t dsto;
    if (bid < 3072) {
        const int idx = bid*256 + t;
        const int m = idx / 48;
        const int k0 = (idx % 48) * 8;
        if (k0 + 7 < En) {
            const float4* p = (const float4*)(we + (size_t)__ldg(&sents[m])*En + k0);
            const float4 x0 = p[0], x1 = p[1];
            v[0]=x0.x; v[1]=x0.y; v[2]=x0.z; v[3]=x0.w;
            v[4]=x1.x; v[5]=x1.y; v[6]=x1.z; v[7]=x1.w;
        } else {
            const int s = sents[m], mk = masks[m];
            #pragma unroll
            for (int j=0;j<8;j++){
                const int k = k0+j;
                v[j] = (k < En) ? we[(size_t)s*En + k]
                     : (k < Dn) ? me[(size_t)mk*Mn + (k-En)] : 0.f;
            }
        }
        dsto = ((size_t)m*KPAD + k0)*2;
        unsigned hw[4], lw[4];
        #pragma unroll
        for (int j=0;j<4;j++) splitpack(v[2*j], v[2*j+1], hw[j], lw[j]);
        *(uint4*)((char*)g_A_hi + dsto) = make_uint4(hw[0],hw[1],hw[2],hw[3]);
        *(uint4*)((char*)g_A_lo + dsto) = make_uint4(lw[0],lw[1],lw[2],lw[3]);
    } else {
        const int idx = (bid-3072)*256 + t;
        const int d = idx / (Gn*48);
        const int rem = idx % (Gn*48);
        const int n = rem / 48;
        const int k0 = (rem % 48) * 8;
        const float* __restrict__ W = d ? w_ih_b : w_ih_f;
        #pragma unroll
        for (int j=0;j<8;j++){
            const int k = k0+j;
            v[j] = (k < Dn) ? W[(size_t)n*Dn + k] : 0.f;
        }
        dsto = (((size_t)d*Gn + n)*KPAD + k0)*2;
        unsigned hw[4], lw[4];
        #pragma unroll
        for (int j=0;j<4;j++) splitpack(v[2*j], v[2*j+1], hw[j], lw[j]);
        *(uint4*)((char*)g_B_hi + dsto) = make_uint4(hw[0],hw[1],hw[2],hw[3]);
        *(uint4*)((char*)g_B_lo + dsto) = make_uint4(lw[0],lw[1],lw[2],lw[3]);
    }
}

// ---------------------------------------------------------------------------
// Kernel 1: bf16 hi/lo tensor-core GEMM -> fp32 gates (+bias). (unchanged)
// ---------------------------------------------------------------------------
#define NKT 12
#define GROW 80
#define GBUF (128*GROW)
#define GSM_AH 0
#define GSM_AL (2*GBUF)
#define GSM_BH (4*GBUF)
#define GSM_BL (6*GBUF)
#define GSM_BIAS (8*GBUF)
#define GEMM_SMEM (8*GBUF + 512)

__global__ void __launch_bounds__(256, 2)
gemm_gates_kernel(const int* __restrict__ lens,
                  const float* __restrict__ b_ih_f, const float* __restrict__ b_hh_f,
                  const float* __restrict__ b_ih_b, const float* __restrict__ b_hh_b) {
    extern __shared__ char gsm[];
    const int dir = blockIdx.z;
    const int bx = blockIdx.x;
    const int m0 = bx*128;
    const int n0 = blockIdx.y*128;
    if ((bx & 1)*128 >= lens[bx >> 1]) return;

    const float* __restrict__ bih = dir ? b_ih_b : b_ih_f;
    const float* __restrict__ bhh = dir ? b_hh_b : b_hh_f;
    float* __restrict__ C = dir ? g_gates_b : g_gates_f;

    const int tid = threadIdx.x;
    float* bias_s = (float*)(gsm + GSM_BIAS);
    if (tid < 128) bias_s[tid] = bih[n0+tid] + bhh[n0+tid];

    const unsigned smb = (unsigned)__cvta_generic_to_shared(gsm);

    const int cg = tid & 3, r0 = tid >> 2;
    const __nv_bfloat16* __restrict__ Ahi = g_A_hi + (size_t)m0*KPAD;
    const __nv_bfloat16* __restrict__ Alo = g_A_lo + (size_t)m0*KPAD;
    const __nv_bfloat16* __restrict__ Bhi = g_B_hi + ((size_t)dir*Gn + n0)*KPAD;
    const __nv_bfloat16* __restrict__ Blo = g_B_lo + ((size_t)dir*Gn + n0)*KPAD;

    auto issue = [&](int kt, int buf){
        const int kb = kt*32 + cg*8;
        const unsigned bufo = buf*GBUF;
        #pragma unroll
        for (int p = 0; p < 2; p++){
            const int r = r0 + p*64;
            const unsigned d0 = bufo + r*GROW + cg*16;
            const size_t so = (size_t)r*KPAD + kb;
            cpasync16(smb + GSM_AH + d0, Ahi + so);
            cpasync16(smb + GSM_AL + d0, Alo + so);
            cpasync16(smb + GSM_BH + d0, Bhi + so);
            cpasync16(smb + GSM_BL + d0, Blo + so);
        }
        asm volatile("cp.async.commit_group;");
    };

    const int lane = tid & 31, wid = tid >> 5;
    const int wm = wid >> 2, wn = wid & 3;

    float acc[4][4][4];
    #pragma unroll
    for (int i=0;i<4;i++)
        #pragma unroll
        for (int a=0;a<4;a++)
            #pragma unroll
            for (int c=0;c<4;c++) acc[i][a][c] = 0.f;

    const int a_r = lane & 15, a_k8 = lane >> 4;
    const int b_r = lane & 7, b_h = (lane >> 3) & 1, b_k8 = lane >> 4;
    const unsigned a_base = (wm*64 + a_r)*GROW + a_k8*16;
    const unsigned b_base = (wn*32 + b_h*8 + b_r)*GROW + b_k8*16;

    issue(0, 0);
    asm volatile("cp.async.wait_group 0;");
    __syncthreads();

    for (int kt = 0; kt < NKT; kt++){
        const int buf = kt & 1;
        if (kt < NKT-1) issue(kt+1, buf^1);
        const unsigned bufo = buf*GBUF;
        #pragma unroll
        for (int kk = 0; kk < 2; kk++){
            unsigned ah[4][4], al[4][4], bh[2][4], bl[2][4];
            #pragma unroll
            for (int i=0;i<4;i++){
                const unsigned aoff = bufo + a_base + i*16*GROW + kk*32;
                LDSM4(ah[i][0],ah[i][1],ah[i][2],ah[i][3], smb + GSM_AH + aoff);
                LDSM4(al[i][0],al[i][1],al[i][2],al[i][3], smb + GSM_AL + aoff);
            }
            #pragma unroll
            for (int j=0;j<2;j++){
                const unsigned boff = bufo + b_base + j*16*GROW + kk*32;
                LDSM4(bh[j][0],bh[j][1],bh[j][2],bh[j][3], smb + GSM_BH + boff);
                LDSM4(bl[j][0],bl[j][1],bl[j][2],bl[j][3], smb + GSM_BL + boff);
            }
            #pragma unroll
            for (int i=0;i<4;i++)
                #pragma unroll
                for (int a=0;a<4;a++){
                    const int j = a>>1, s = a&1;
                    MMA_BF16(acc[i][a], ah[i], bh[j][s], bh[j][2+s]);
                    MMA_BF16(acc[i][a], al[i], bh[j][s], bh[j][2+s]);
                    MMA_BF16(acc[i][a], ah[i], bl[j][s], bl[j][2+s]);
                }
        }
        if (kt < NKT-1) asm volatile("cp.async.wait_group 0;");
        __syncthreads();
    }

    const int g = lane >> 2, q = lane & 3;
    #pragma unroll
    for (int i=0;i<4;i++){
        const int m = m0 + wm*64 + i*16 + g;
        float* c0p = C + (size_t)m*Gn + n0 + wn*32;
        float* c1p = C + (size_t)(m+8)*Gn + n0 + wn*32;
        #pragma unroll
        for (int a=0;a<4;a++){
            const int nn = a*8 + 2*q;
            const float bb0 = bias_s[wn*32 + nn], bb1 = bias_s[wn*32 + nn + 1];
            *(float2*)(c0p + nn) = make_float2(acc[i][a][0] + bb0, acc[i][a][1] + bb1);
            *(float2*)(c1p + nn) = make_float2(acc[i][a][2] + bb0, acc[i][a][3] + bb1);
        }
    }
}

// ---------------------------------------------------------------------------
// Kernel 2: LSTM recurrence, SPLIT-K: 512 threads, lane pairs (l, l^16)
// split k in half; combine via shfl_xor(16). 16 warps/SM for latency hiding.
// ---------------------------------------------------------------------------
#define HPAD 136   // 2x(64 + 4pad + 64 + 4pad) floats per buffer
#define LSTM_SMEM (2*KSQ*512*16 + 2*HPAD*4)

__global__ void __launch_bounds__(512, 1)
lstm_kernel(const int* __restrict__ lens) {
    extern __shared__ ulonglong2 smem_v[];
    ulonglong2* sA = smem_v;                       // [KSQ][512]
    ulonglong2* sB = smem_v + KSQ*512;             // [KSQ][512]
    float* hs = (float*)(smem_v + 2*KSQ*512);      // [2][HPAD]

    const int bx  = blockIdx.x;
    const int dir = bx >> 6;
    const int row = bx & 63;
    const float* __restrict__ gates_in = dir ? g_gates_b : g_gates_f;
    float* __restrict__ h_out          = dir ? g_hb : g_hf;

    const int tid = threadIdx.x;
    const int lane = tid & 31;
    const int wrp = tid >> 5;
    const int gp = wrp*16 + (lane & 15);
    const int khalf = lane >> 4;
    const int e = gp >> 1, ghalf = gp & 1;
    const int gA = ghalf*128 + e;
    const int len = lens[row];
    const bool exlane = (khalf == 0);
    const bool writer = (khalf == 0) && (ghalf == 0);

    // register weight chunks
    ulonglong2 wA[KRQ], wB[KRQ];
    {
        const ulonglong2* __restrict__ grA = g_wrA + (size_t)dir*KRQ*512;
        const ulonglong2* __restrict__ grB = g_wrB + (size_t)dir*KRQ*512;
        #pragma unroll
        for (int j = 0; j < KRQ; j++) {
            wA[j] = grA[j*512 + tid];
            wB[j] = grB[j*512 + tid];
        }
    }
    // smem weight chunks
    {
        const ulonglong2* __restrict__ gsA = g_wsA + (size_t)dir*KSQ*512;
        const ulonglong2* __restrict__ gsB = g_wsB + (size_t)dir*KSQ*512;
        #pragma unroll
        for (int j = 0; j < KSQ; j++) {
            sA[j*512 + tid] = gsA[j*512 + tid];
            sB[j*512 + tid] = gsB[j*512 + tid];
        }
    }
    if (tid < 2*HPAD) hs[tid] = 0.f;
    float c_reg = 0.f;

    // h base offset for this thread's k-half: khalf0 -> 0, khalf1 -> 68 floats
    const int hoff = khalf * 68;

    // prologue ex loads
    float exA = 0.f, exB = 0.f;
    if (exlane) {
        const int u0 = dir ? (len-1) : 0;
        const size_t base = ((size_t)row*Ln + u0)*Gn;
        exA = gates_in[base + gA];
        exB = gates_in[base + gA + 256];
    }
    __syncthreads();

    for (int t = 0; t < len; t++) {
        const int buf = t & 1;
        const float* hcur = hs + buf*HPAD + hoff;
        float* hnxt = hs + (buf^1)*HPAD;

        // prefetch next ex
        float nA = 0.f, nB = 0.f;
        if (exlane && t+1 < len) {
            const int un = dir ? (len-2-t) : (t+1);
            const size_t b2 = ((size_t)row*Ln + un)*Gn;
            nA = gates_in[b2 + gA];
            nB = gates_in[b2 + gA + 256];
        }

        ull a0=0, a1=0, b0=0, b1=0;
        #pragma unroll
        for (int j = 0; j < KRQ; j++) {
            const ulonglong2 hv = *(const ulonglong2*)&hcur[4*j];
            ffma2(a0, wA[j].x, hv.x); ffma2(a1, wA[j].y, hv.y);
            ffma2(b0, wB[j].x, hv.x); ffma2(b1, wB[j].y, hv.y);
        }
        #pragma unroll
        for (int j = 0; j < KSQ; j++) {
            const ulonglong2 hv = *(const ulonglong2*)&hcur[4*(KRQ+j)];
            const ulonglong2 wa = sA[j*512 + tid];
            const ulonglong2 wb = sB[j*512 + tid];
            ffma2(a0, wa.x, hv.x); ffma2(a1, wa.y, hv.y);
            ffma2(b0, wb.x, hv.x); ffma2(b1, wb.y, hv.y);
        }
        const float2 fa = unpk(addf2(a0, a1));
        const float2 fb = unpk(addf2(b0, b1));
        float pAv = fa.x + fa.y;
        float pBv = fb.x + fb.y;
        // combine k-halves
        pAv += __shfl_xor_sync(0xffffffffu, pAv, 16);
        pBv += __shfl_xor_sync(0xffffffffu, pBv, 16);
        const float gAv = pAv + exA;   // valid on exlanes
        const float gBv = pBv + exB;
        // pair exchange (ghalf): lanes (2j, 2j+1) within lower half
        const float qA = __shfl_xor_sync(0xffffffffu, gAv, 1);
        const float qB = __shfl_xor_sync(0xffffffffu, gBv, 1);

        if (writer) {
            // this lane: ghalf=0 -> gAv=i, gBv=g; partner: qA=f, qB=o
            const float c = sigf(qA)*c_reg + sigf(gAv)*tanha(gBv);
            const float h = sigf(qB)*tanha(c);
            c_reg = c;
            const int u = dir ? (len-1-t) : t;
            const int st = (e < 64) ? e : (e + 4);
            hnxt[st] = h;
            h_out[((size_t)row*Ln + u)*HDn + e] = h;
        }
        exA = nA; exB = nB;
        __syncthreads();
    }
}

// ---------------------------------------------------------------------------
// Kernel 3: CRF + classifier + fused finalize (last block reduces).
// ---------------------------------------------------------------------------
__global__ void __launch_bounds__(256)
crf_kernel(const int* __restrict__ masks,
           const int* __restrict__ lens,
           const int* __restrict__ labels,
           const float* __restrict__ f2t_w,
           const float* __restrict__ f2t_b,
           const float* __restrict__ trans,
           const float* __restrict__ f2l_w,
           const float* __restrict__ f2l_b,
           float* __restrict__ out) {
    const int b = blockIdx.x;
    const int tid = threadIdx.x;

    __shared__ float tv[Hn];
    __shared__ float fw[2*Hn];
    __shared__ float em[Ln][2];
    __shared__ float al[Ln][2];
    __shared__ float be[Ln][2];
    __shared__ float sp[Ln];
    __shared__ float red[Hn];
    __shared__ int   msk[Ln];
    __shared__ float Ts[4];
    __shared__ float logZ_s, sumsp_s, scores[3];
    __shared__ unsigned lastflag;

    const int len = lens[b];
    msk[tid] = masks[b*Ln + tid];
    fw[tid]      = f2t_w[tid];
    fw[Hn + tid] = f2t_w[Hn + tid];
    if (tid < 4) Ts[tid] = trans[tid];
    __syncthreads();

    const float* __restrict__ hfb = g_hf + (size_t)b*Ln*HDn;
    const float* __restrict__ hbb = g_hb + (size_t)b*Ln*HDn;
    const float* __restrict__ hsel = (tid < HDn) ? (hfb + tid) : (hbb + tid - HDn);

    // tavg: skip unmasked positions (warp-uniform branch; masks are sparse)
    float num = 0.f; int cnt = 0;
    for (int l = 0; l < Ln; l++) {
        const int mf = msk[l];
        if (mf) {
            num += hsel[l*HDn] * (float)mf;
            cnt += mf;
        }
    }
    tv[tid] = num / (float)cnt;
    __syncthreads();

    {
        const int warp = tid >> 5, lane = tid & 31;
        const float b0 = f2t_b[0], b1 = f2t_b[1];
        for (int l = warp; l < len; l += 8) {
            const float* hr  = hfb + l*HDn;
            const float* hr2 = hbb + l*HDn;
            float e0 = 0.f, e1 = 0.f;
            #pragma unroll
            for (int q = 0; q < 4; q++) {
                const int hh = lane + q*32;
                const float c  = hr[hh]  + tv[hh];
                const float c2 = hr2[hh] + tv[HDn + hh];
                e0 += c*fw[hh]      + c2*fw[HDn+hh];
                e1 += c*fw[Hn+hh]   + c2*fw[Hn+HDn+hh];
            }
            #pragma unroll
            for (int off = 16; off; off >>= 1) {
                e0 += __shfl_xor_sync(0xffffffffu, e0, off);
                e1 += __shfl_xor_sync(0xffffffffu, e1, off);
            }
            if (lane == 0) { em[l][0] = e0 + b0; em[l][1] = e1 + b1; }
        }
    }
    __syncthreads();

    if (tid == 0) {
        al[0][0]=em[0][0]; al[0][1]=em[0][1];
        for (int t = 1; t < len; t++) {
            const float a0 = al[t-1][0], a1 = al[t-1][1];
            al[t][0] = em[t][0] + lse2(a0+Ts[0], a1+Ts[2]);
            al[t][1] = em[t][1] + lse2(a0+Ts[1], a1+Ts[3]);
        }
        logZ_s = lse2(al[len-1][0], al[len-1][1]);
    }
    if (tid == 128) {
        be[len-1][0]=0.f; be[len-1][1]=0.f;
        for (int t = len-2; t >= 0; t--) {
            const float x0 = em[t+1][0]+be[t+1][0];
            const float x1 = em[t+1][1]+be[t+1][1];
            be[t][0] = lse2(Ts[0]+x0, Ts[1]+x1);
            be[t][1] = lse2(Ts[2]+x0, Ts[3]+x1);
        }
    }
    __syncthreads();

    sp[tid] = (tid < len) ? __expf(al[tid][1]+be[tid][1]-logZ_s) : 0.f;
    __syncthreads();

    red[tid] = sp[tid];
    __syncthreads();
    for (int s = 128; s > 0; s >>= 1) {
        if (tid < s) red[tid] += red[tid+s];
        __syncthreads();
    }
    if (tid == 0) sumsp_s = red[0];
    __syncthreads();
    const float sum_sp = sumsp_s;

    float s1 = 0.f;
    #pragma unroll 8
    for (int l = 0; l < Ln; l++) s1 += sp[l] * hsel[l*HDn];
    const float svh = s1 + sum_sp * tv[tid];

    for (int c = 0; c < 3; c++) {
        red[tid] = svh * f2l_w[c*Hn + tid];
        __syncthreads();
        for (int s = 128; s > 0; s >>= 1) {
            if (tid < s) red[tid] += red[tid+s];
            __syncthreads();
        }
        if (tid == 0) scores[c] = red[0] + f2l_b[c];
        __syncthreads();
    }

    if (tid == 0) {
        const float m = fmaxf(scores[0], fmaxf(scores[1], scores[2]));
        const float lse = m + __logf(__expf(scores[0]-m)+__expf(scores[1]-m)+__expf(scores[2]-m));
        g_cls[b]   = lse - scores[labels[b]];
        g_spsum[b] = sum_sp;
        __threadfence();
        lastflag = (atomicAdd(&g_crf_done, 1u) == Bn-1) ? 1u : 0u;
    }
    __syncthreads();

    // last block to finish computes the final outputs (deterministic sum order)
    if (lastflag) {
        if (tid < 64) { red[tid] = g_cls[tid]; red[64+tid] = g_spsum[tid]; }
        __syncthreads();
        for (int s = 32; s > 0; s >>= 1) {
            if (tid < s) { red[tid] += red[tid+s]; red[64+tid] += red[64+tid+s]; }
            __syncthreads();
        }
        if (tid == 0) {
            const float pena = fmaxf(Ts[2]-Ts[0], 0.f) + fmaxf(Ts[1]-Ts[3], 0.f);
            out[0] = red[0] / (float)Bn;
            out[1] = 1.0f*pena + 0.1f*(red[64]/(float)Bn);
            g_crf_done = 0;   // reset for next graph replay
        }
    }
}

extern "C" void kernel_launch(void* const* d_in, const int* in_sizes, int n_in,
                              void* d_out, int out_size) {
    const int*   sents      = (const int*)d_in[0];
    const int*   masks      = (const int*)d_in[1];
    const int*   labels     = (const int*)d_in[2];
    const int*   lens       = (const int*)d_in[3];
    const float* word_embed = (const float*)d_in[4];
    const float* mask_embed = (const float*)d_in[5];
    const float* w_ih_f     = (const float*)d_in[6];
    const float* w_hh_f     = (const float*)d_in[7];
    const float* b_ih_f     = (const float*)d_in[8];
    const float* b_hh_f     = (const float*)d_in[9];
    const float* w_ih_b     = (const float*)d_in[10];
    const float* w_hh_b     = (const float*)d_in[11];
    const float* b_ih_b     = (const float*)d_in[12];
    const float* b_hh_b     = (const float*)d_in[13];
    const float* f2t_w      = (const float*)d_in[14];
    const float* f2t_b      = (const float*)d_in[15];
    const float* trans      = (const float*)d_in[16];
    const float* f2l_w      = (const float*)d_in[17];
    const float* f2l_b      = (const float*)d_in[18];
    float* out = (float*)d_out;

    cudaFuncSetAttribute(lstm_kernel,
                         cudaFuncAttributeMaxDynamicSharedMemorySize, LSTM_SMEM);
    cudaFuncSetAttribute(gemm_gates_kernel,
                         cudaFuncAttributeMaxDynamicSharedMemorySize, GEMM_SMEM);

    prep_w_kernel<<<64, 256>>>(w_hh_f, w_hh_b);                   // launch 1
    prep_ab_kernel<<<3264, 256>>>(sents, masks,                   // launch 2
                                  word_embed, mask_embed, w_ih_f, w_ih_b);
    dim3 ggrid(Bn*Ln/128, Gn/128, 2);
    gemm_gates_kernel<<<ggrid, 256, GEMM_SMEM>>>(lens,            // launch 3
                                                 b_ih_f, b_hh_f, b_ih_b, b_hh_b);
    lstm_kernel<<<2*Bn, 512, LSTM_SMEM>>>(lens);                  // launch 4 (captured)
    crf_kernel<<<Bn, 256>>>(masks, lens, labels, f2t_w, f2t_b,    // launch 5
                            trans, f2l_w, f2l_b, out);
}

// round 13
// speedup vs baseline: 1.0970x; 1.0970x over previous
#include <cuda_runtime.h>
#include <cuda_bf16.h>
#include <math.h>

#define Bn 64
#define Ln 256
#define En 300
#define Mn 50
#define Dn 350
#define HDn 128
#define Gn 512   // 4*HD
#define Hn 256
#define KPAD 384

typedef unsigned long long ull;

// Scratch (device globals; no allocation allowed)
__device__ float g_gates_f[Bn*Ln*Gn];
__device__ float g_gates_b[Bn*Ln*Gn];
__device__ float g_hf[Bn*Ln*HDn];
__device__ float g_hb[Bn*Ln*HDn];
// GEMM bf16 hi/lo operand scratch
__device__ __nv_bfloat16 g_A_hi[(size_t)Bn*Ln*KPAD];
__device__ __nv_bfloat16 g_A_lo[(size_t)Bn*Ln*KPAD];
__device__ __nv_bfloat16 g_B_hi[2*Gn*KPAD];
__device__ __nv_bfloat16 g_B_lo[2*Gn*KPAD];
// LSTM weights, thread-mapped (R11 layout: 256 threads, 2 gates each)
#define KRQ 24
#define KSQ 8
__device__ ulonglong2 g_wrA[2*KRQ*256];
__device__ ulonglong2 g_wrB[2*KRQ*256];
__device__ ulonglong2 g_wsA[2*KSQ*256];
__device__ ulonglong2 g_wsB[2*KSQ*256];
__device__ float g_cls[Bn];
__device__ float g_spsum[Bn];
__device__ unsigned g_crf_done;   // zero-init; self-resetting completion counter

// Fast activations: MUFU.TANH based
__device__ __forceinline__ float tanha(float x){
    float r; asm("tanh.approx.f32 %0, %1;" : "=f"(r) : "f"(x)); return r;
}
__device__ __forceinline__ float sigf(float x){
    return fmaf(tanha(0.5f*x), 0.5f, 0.5f);
}
__device__ __forceinline__ float lse2(float a, float b){
    float m = fmaxf(a,b);
    return m + __logf(__expf(a-m)+__expf(b-m));
}
__device__ __forceinline__ void ffma2(ull &d, ull a, ull b){
    asm("fma.rn.f32x2 %0, %1, %2, %0;" : "+l"(d) : "l"(a), "l"(b));
}
__device__ __forceinline__ ull addf2(ull a, ull b){
    ull r; asm("add.rn.f32x2 %0, %1, %2;" : "=l"(r) : "l"(a), "l"(b)); return r;
}
__device__ __forceinline__ ull pack2(float lo, float hi){
    ull r; asm("mov.b64 %0, {%1, %2};" : "=l"(r) : "r"(__float_as_uint(lo)), "r"(__float_as_uint(hi))); return r;
}
__device__ __forceinline__ float2 unpk(ull v){
    unsigned lo, hi; asm("mov.b64 {%0, %1}, %2;" : "=r"(lo), "=r"(hi) : "l"(v));
    return make_float2(__uint_as_float(lo), __uint_as_float(hi));
}
__device__ __forceinline__ void splitpack(float a, float b, unsigned &hw, unsigned &lw){
    __nv_bfloat16 ha = __float2bfloat16_rn(a);
    __nv_bfloat16 hb = __float2bfloat16_rn(b);
    __nv_bfloat16 la = __float2bfloat16_rn(a - __bfloat162float(ha));
    __nv_bfloat16 lb = __float2bfloat16_rn(b - __bfloat162float(hb));
    hw = ((unsigned)__bfloat16_as_ushort(hb) << 16) | (unsigned)__bfloat16_as_ushort(ha);
    lw = ((unsigned)__bfloat16_as_ushort(lb) << 16) | (unsigned)__bfloat16_as_ushort(la);
}
__device__ __forceinline__ void cpasync16(unsigned dst, const void* src){
    asm volatile("cp.async.cg.shared.global [%0], [%1], 16;" :: "r"(dst), "l"(src));
}
#define LDSM4(d0,d1,d2,d3,addr) \
    asm volatile("ldmatrix.sync.aligned.m8n8.x4.shared.b16 {%0,%1,%2,%3}, [%4];" \
        : "=r"(d0),"=r"(d1),"=r"(d2),"=r"(d3) : "r"(addr))
#define MMA_BF16(c,a,b0v,b1v) \
    asm volatile("mma.sync.aligned.m16n8k16.row.col.f32.bf16.bf16.f32 " \
        "{%0,%1,%2,%3}, {%4,%5,%6,%7}, {%8,%9}, {%0,%1,%2,%3};" \
        : "+f"(c[0]),"+f"(c[1]),"+f"(c[2]),"+f"(c[3]) \
        : "r"(a[0]),"r"(a[1]),"r"(a[2]),"r"(a[3]), "r"(b0v),"r"(b1v))

// ---------------------------------------------------------------------------
// Kernel 0: LSTM thread-mapped weight chunks, both dirs (R11 layout).
// ---------------------------------------------------------------------------
__global__ void prep_w_kernel(const float* __restrict__ w_f,
                              const float* __restrict__ w_b) {
    const int idx = blockIdx.x*256 + threadIdx.x;   // [0, 16384)
    const int d = idx >> 13;
    const int r = idx & 8191;
    const int q = r >> 8;        // [0,32)
    const int t = r & 255;
    const float* __restrict__ w = d ? w_b : w_f;
    const int e = t >> 1, half = t & 1;
    const int gA = half*128 + e;
    const int gB = gA + 256;
    const float4 a = *(const float4*)&w[(size_t)gA*HDn + 4*q];
    const float4 b = *(const float4*)&w[(size_t)gB*HDn + 4*q];
    ulonglong2 ua, ub;
    ua.x = pack2(a.x, a.y); ua.y = pack2(a.z, a.w);
    ub.x = pack2(b.x, b.y); ub.y = pack2(b.z, b.w);
    if (q < KRQ) {
        g_wrA[((size_t)d*KRQ + q)*256 + t] = ua;
        g_wrB[((size_t)d*KRQ + q)*256 + t] = ub;
    } else {
        g_wsA[((size_t)d*KSQ + (q-KRQ))*256 + t] = ua;
        g_wsB[((size_t)d*KSQ + (q-KRQ))*256 + t] = ub;
    }
}

// ---------------------------------------------------------------------------
// Kernel 0b: build bf16 hi/lo GEMM operands.
// ---------------------------------------------------------------------------
__global__ void __launch_bounds__(256)
prep_ab_kernel(const int* __restrict__ sents, const int* __restrict__ masks,
               const float* __restrict__ we, const float* __restrict__ me,
               const float* __restrict__ w_ih_f, const float* __restrict__ w_ih_b) {
    const int bid = blockIdx.x;
    const int t = threadIdx.x;
    float v[8];
    size_t dsto;
    if (bid < 3072) {
        const int idx = bid*256 + t;
        const int m = idx / 48;
        const int k0 = (idx % 48) * 8;
        if (k0 + 7 < En) {
            const float4* p = (const float4*)(we + (size_t)__ldg(&sents[m])*En + k0);
            const float4 x0 = p[0], x1 = p[1];
            v[0]=x0.x; v[1]=x0.y; v[2]=x0.z; v[3]=x0.w;
            v[4]=x1.x; v[5]=x1.y; v[6]=x1.z; v[7]=x1.w;
        } else {
            const int s = sents[m], mk = masks[m];
            #pragma unroll
            for (int j=0;j<8;j++){
                const int k = k0+j;
                v[j] = (k < En) ? we[(size_t)s*En + k]
                     : (k < Dn) ? me[(size_t)mk*Mn + (k-En)] : 0.f;
            }
        }
        dsto = ((size_t)m*KPAD + k0)*2;
        unsigned hw[4], lw[4];
        #pragma unroll
        for (int j=0;j<4;j++) splitpack(v[2*j], v[2*j+1], hw[j], lw[j]);
        *(uint4*)((char*)g_A_hi + dsto) = make_uint4(hw[0],hw[1],hw[2],hw[3]);
        *(uint4*)((char*)g_A_lo + dsto) = make_uint4(lw[0],lw[1],lw[2],lw[3]);
    } else {
        const int idx = (bid-3072)*256 + t;
        const int d = idx / (Gn*48);
        const int rem = idx % (Gn*48);
        const int n = rem / 48;
        const int k0 = (rem % 48) * 8;
        const float* __restrict__ W = d ? w_ih_b : w_ih_f;
        #pragma unroll
        for (int j=0;j<8;j++){
            const int k = k0+j;
            v[j] = (k < Dn) ? W[(size_t)n*Dn + k] : 0.f;
        }
        dsto = (((size_t)d*Gn + n)*KPAD + k0)*2;
        unsigned hw[4], lw[4];
        #pragma unroll
        for (int j=0;j<4;j++) splitpack(v[2*j], v[2*j+1], hw[j], lw[j]);
        *(uint4*)((char*)g_B_hi + dsto) = make_uint4(hw[0],hw[1],hw[2],hw[3]);
        *(uint4*)((char*)g_B_lo + dsto) = make_uint4(lw[0],lw[1],lw[2],lw[3]);
    }
}

// ---------------------------------------------------------------------------
// Kernel 1: bf16 hi/lo tensor-core GEMM -> fp32 gates (+bias).
// ---------------------------------------------------------------------------
#define NKT 12
#define GROW 80
#define GBUF (128*GROW)
#define GSM_AH 0
#define GSM_AL (2*GBUF)
#define GSM_BH (4*GBUF)
#define GSM_BL (6*GBUF)
#define GSM_BIAS (8*GBUF)
#define GEMM_SMEM (8*GBUF + 512)

__global__ void __launch_bounds__(256, 2)
gemm_gates_kernel(const int* __restrict__ lens,
                  const float* __restrict__ b_ih_f, const float* __restrict__ b_hh_f,
                  const float* __restrict__ b_ih_b, const float* __restrict__ b_hh_b) {
    extern __shared__ char gsm[];
    const int dir = blockIdx.z;
    const int bx = blockIdx.x;
    const int m0 = bx*128;
    const int n0 = blockIdx.y*128;
    if ((bx & 1)*128 >= lens[bx >> 1]) return;

    const float* __restrict__ bih = dir ? b_ih_b : b_ih_f;
    const float* __restrict__ bhh = dir ? b_hh_b : b_hh_f;
    float* __restrict__ C = dir ? g_gates_b : g_gates_f;

    const int tid = threadIdx.x;
    float* bias_s = (float*)(gsm + GSM_BIAS);
    if (tid < 128) bias_s[tid] = bih[n0+tid] + bhh[n0+tid];

    const unsigned smb = (unsigned)__cvta_generic_to_shared(gsm);

    const int cg = tid & 3, r0 = tid >> 2;
    const __nv_bfloat16* __restrict__ Ahi = g_A_hi + (size_t)m0*KPAD;
    const __nv_bfloat16* __restrict__ Alo = g_A_lo + (size_t)m0*KPAD;
    const __nv_bfloat16* __restrict__ Bhi = g_B_hi + ((size_t)dir*Gn + n0)*KPAD;
    const __nv_bfloat16* __restrict__ Blo = g_B_lo + ((size_t)dir*Gn + n0)*KPAD;

    auto issue = [&](int kt, int buf){
        const int kb = kt*32 + cg*8;
        const unsigned bufo = buf*GBUF;
        #pragma unroll
        for (int p = 0; p < 2; p++){
            const int r = r0 + p*64;
            const unsigned d0 = bufo + r*GROW + cg*16;
            const size_t so = (size_t)r*KPAD + kb;
            cpasync16(smb + GSM_AH + d0, Ahi + so);
            cpasync16(smb + GSM_AL + d0, Alo + so);
            cpasync16(smb + GSM_BH + d0, Bhi + so);
            cpasync16(smb + GSM_BL + d0, Blo + so);
        }
        asm volatile("cp.async.commit_group;");
    };

    const int lane = tid & 31, wid = tid >> 5;
    const int wm = wid >> 2, wn = wid & 3;

    float acc[4][4][4];
    #pragma unroll
    for (int i=0;i<4;i++)
        #pragma unroll
        for (int a=0;a<4;a++)
            #pragma unroll
            for (int c=0;c<4;c++) acc[i][a][c] = 0.f;

    const int a_r = lane & 15, a_k8 = lane >> 4;
    const int b_r = lane & 7, b_h = (lane >> 3) & 1, b_k8 = lane >> 4;
    const unsigned a_base = (wm*64 + a_r)*GROW + a_k8*16;
    const unsigned b_base = (wn*32 + b_h*8 + b_r)*GROW + b_k8*16;

    issue(0, 0);
    asm volatile("cp.async.wait_group 0;");
    __syncthreads();

    for (int kt = 0; kt < NKT; kt++){
        const int buf = kt & 1;
        if (kt < NKT-1) issue(kt+1, buf^1);
        const unsigned bufo = buf*GBUF;
        #pragma unroll
        for (int kk = 0; kk < 2; kk++){
            unsigned ah[4][4], al[4][4], bh[2][4], bl[2][4];
            #pragma unroll
            for (int i=0;i<4;i++){
                const unsigned aoff = bufo + a_base + i*16*GROW + kk*32;
                LDSM4(ah[i][0],ah[i][1],ah[i][2],ah[i][3], smb + GSM_AH + aoff);
                LDSM4(al[i][0],al[i][1],al[i][2],al[i][3], smb + GSM_AL + aoff);
            }
            #pragma unroll
            for (int j=0;j<2;j++){
                const unsigned boff = bufo + b_base + j*16*GROW + kk*32;
                LDSM4(bh[j][0],bh[j][1],bh[j][2],bh[j][3], smb + GSM_BH + boff);
                LDSM4(bl[j][0],bl[j][1],bl[j][2],bl[j][3], smb + GSM_BL + boff);
            }
            #pragma unroll
            for (int i=0;i<4;i++)
                #pragma unroll
                for (int a=0;a<4;a++){
                    const int j = a>>1, s = a&1;
                    MMA_BF16(acc[i][a], ah[i], bh[j][s], bh[j][2+s]);
                    MMA_BF16(acc[i][a], al[i], bh[j][s], bh[j][2+s]);
                    MMA_BF16(acc[i][a], ah[i], bl[j][s], bl[j][2+s]);
                }
        }
        if (kt < NKT-1) asm volatile("cp.async.wait_group 0;");
        __syncthreads();
    }

    const int g = lane >> 2, q = lane & 3;
    #pragma unroll
    for (int i=0;i<4;i++){
        const int m = m0 + wm*64 + i*16 + g;
        float* c0p = C + (size_t)m*Gn + n0 + wn*32;
        float* c1p = C + (size_t)(m+8)*Gn + n0 + wn*32;
        #pragma unroll
        for (int a=0;a<4;a++){
            const int nn = a*8 + 2*q;
            const float bb0 = bias_s[wn*32 + nn], bb1 = bias_s[wn*32 + nn + 1];
            *(float2*)(c0p + nn) = make_float2(acc[i][a][0] + bb0, acc[i][a][1] + bb1);
            *(float2*)(c1p + nn) = make_float2(acc[i][a][2] + bb0, acc[i][a][3] + bb1);
        }
    }
}

// ---------------------------------------------------------------------------
// Kernel 2: LSTM recurrence (R11 winner: 256 threads, tanh.approx).
// ---------------------------------------------------------------------------
#define LSTM_SMEM (2*KSQ*256*16 + 2*128*4)

__global__ void __launch_bounds__(256, 1)
lstm_kernel(const int* __restrict__ lens) {
    extern __shared__ ulonglong2 smem_v[];
    ulonglong2* sA = smem_v;
    ulonglong2* sB = smem_v + KSQ*256;
    float* hs = (float*)(smem_v + 2*KSQ*256);

    const int bx  = blockIdx.x;
    const int dir = bx >> 6;
    const int row = bx & 63;
    const float* __restrict__ gates_in = dir ? g_gates_b : g_gates_f;
    float* __restrict__ h_out          = dir ? g_hb : g_hf;

    const int tid = threadIdx.x;
    const int e = tid >> 1, half = tid & 1;
    const int gA = half*128 + e;
    const int len = lens[row];

    ulonglong2 wA[KRQ], wB[KRQ];
    {
        const ulonglong2* __restrict__ grA = g_wrA + (size_t)dir*KRQ*256;
        const ulonglong2* __restrict__ grB = g_wrB + (size_t)dir*KRQ*256;
        #pragma unroll
        for (int q = 0; q < KRQ; q++) {
            wA[q] = grA[q*256 + tid];
            wB[q] = grB[q*256 + tid];
        }
    }
    {
        const ulonglong2* __restrict__ gsA = g_wsA + (size_t)dir*KSQ*256;
        const ulonglong2* __restrict__ gsB = g_wsB + (size_t)dir*KSQ*256;
        #pragma unroll
        for (int j = 0; j < KSQ; j++) {
            sA[j*256 + tid] = gsA[j*256 + tid];
            sB[j*256 + tid] = gsB[j*256 + tid];
        }
    }
    if (tid < 128) hs[tid] = 0.f;
    float c_reg = 0.f;

    float exA, exB;
    {
        const int u0 = dir ? (len-1) : 0;
        const size_t base = ((size_t)row*Ln + u0)*Gn;
        exA = gates_in[base + gA];
        exB = gates_in[base + gA + 256];
    }
    __syncthreads();

    for (int t = 0; t < len; t++) {
        const int buf = t & 1;
        const float* hcur = hs + buf*128;
        float* hnxt = hs + (buf^1)*128;

        float nA = 0.f, nB = 0.f;
        if (t+1 < len) {
            const int un = dir ? (len-2-t) : (t+1);
            const size_t b2 = ((size_t)row*Ln + un)*Gn;
            nA = gates_in[b2 + gA];
            nB = gates_in[b2 + gA + 256];
        }

        ull a0=0, a1=0, b0=0, b1=0;
        #pragma unroll
        for (int q = 0; q < KRQ; q++) {
            const ulonglong2 hv = *(const ulonglong2*)&hcur[4*q];
            ffma2(a0, wA[q].x, hv.x); ffma2(a1, wA[q].y, hv.y);
            ffma2(b0, wB[q].x, hv.x); ffma2(b1, wB[q].y, hv.y);
        }
        #pragma unroll
        for (int j = 0; j < KSQ; j++) {
            const ulonglong2 hv = *(const ulonglong2*)&hcur[4*(KRQ+j)];
            const ulonglong2 wa = sA[j*256 + tid];
            const ulonglong2 wb = sB[j*256 + tid];
            ffma2(a0, wa.x, hv.x); ffma2(a1, wa.y, hv.y);
            ffma2(b0, wb.x, hv.x); ffma2(b1, wb.y, hv.y);
        }
        const float2 fa = unpk(addf2(a0, a1));
        const float2 fb = unpk(addf2(b0, b1));
        const float gAv = fa.x + fa.y + exA;
        const float gBv = fb.x + fb.y + exB;

        const float pA = __shfl_xor_sync(0xffffffffu, gAv, 1);
        const float pB = __shfl_xor_sync(0xffffffffu, gBv, 1);
        const float gi = half ? pA : gAv;
        const float gg = half ? pB : gBv;
        const float gf = half ? gAv : pA;
        const float go = half ? gBv : pB;

        const float c = sigf(gf)*c_reg + sigf(gi)*tanha(gg);
        const float h = sigf(go)*tanha(c);
        c_reg = c;

        if (!half) {
            const int u = dir ? (len-1-t) : t;
            hnxt[e] = h;
            h_out[((size_t)row*Ln + u)*HDn + e] = h;
        }
        exA = nA; exB = nB;
        __syncthreads();
    }
}

// ---------------------------------------------------------------------------
// Kernel 3: CRF + classifier + fused finalize (last block reduces).
// ---------------------------------------------------------------------------
__global__ void __launch_bounds__(256)
crf_kernel(const int* __restrict__ masks,
           const int* __restrict__ lens,
           const int* __restrict__ labels,
           const float* __restrict__ f2t_w,
           const float* __restrict__ f2t_b,
           const float* __restrict__ trans,
           const float* __restrict__ f2l_w,
           const float* __restrict__ f2l_b,
           float* __restrict__ out) {
    const int b = blockIdx.x;
    const int tid = threadIdx.x;

    __shared__ float tv[Hn];
    __shared__ float fw[2*Hn];
    __shared__ float em[Ln][2];
    __shared__ float al[Ln][2];
    __shared__ float be[Ln][2];
    __shared__ float sp[Ln];
    __shared__ float red[Hn];
    __shared__ int   msk[Ln];
    __shared__ float Ts[4];
    __shared__ float logZ_s, sumsp_s, scores[3];
    __shared__ unsigned lastflag;

    const int len = lens[b];
    msk[tid] = masks[b*Ln + tid];
    fw[tid]      = f2t_w[tid];
    fw[Hn + tid] = f2t_w[Hn + tid];
    if (tid < 4) Ts[tid] = trans[tid];
    __syncthreads();

    const float* __restrict__ hfb = g_hf + (size_t)b*Ln*HDn;
    const float* __restrict__ hbb = g_hb + (size_t)b*Ln*HDn;
    const float* __restrict__ hsel = (tid < HDn) ? (hfb + tid) : (hbb + tid - HDn);

    // tavg: skip unmasked positions (warp-uniform branch; masks are sparse)
    float num = 0.f; int cnt = 0;
    for (int l = 0; l < Ln; l++) {
        const int mf = msk[l];
        if (mf) {
            num += hsel[l*HDn] * (float)mf;
            cnt += mf;
        }
    }
    tv[tid] = num / (float)cnt;
    __syncthreads();

    {
        const int warp = tid >> 5, lane = tid & 31;
        const float b0 = f2t_b[0], b1 = f2t_b[1];
        for (int l = warp; l < len; l += 8) {
            const float* hr  = hfb + l*HDn;
            const float* hr2 = hbb + l*HDn;
            float e0 = 0.f, e1 = 0.f;
            #pragma unroll
            for (int q = 0; q < 4; q++) {
                const int hh = lane + q*32;
                const float c  = hr[hh]  + tv[hh];
                const float c2 = hr2[hh] + tv[HDn + hh];
                e0 += c*fw[hh]      + c2*fw[HDn+hh];
                e1 += c*fw[Hn+hh]   + c2*fw[Hn+HDn+hh];
            }
            #pragma unroll
            for (int off = 16; off; off >>= 1) {
                e0 += __shfl_xor_sync(0xffffffffu, e0, off);
                e1 += __shfl_xor_sync(0xffffffffu, e1, off);
            }
            if (lane == 0) { em[l][0] = e0 + b0; em[l][1] = e1 + b1; }
        }
    }
    __syncthreads();

    if (tid == 0) {
        al[0][0]=em[0][0]; al[0][1]=em[0][1];
        for (int t = 1; t < len; t++) {
            const float a0 = al[t-1][0], a1 = al[t-1][1];
            al[t][0] = em[t][0] + lse2(a0+Ts[0], a1+Ts[2]);
            al[t][1] = em[t][1] + lse2(a0+Ts[1], a1+Ts[3]);
        }
        logZ_s = lse2(al[len-1][0], al[len-1][1]);
    }
    if (tid == 128) {
        be[len-1][0]=0.f; be[len-1][1]=0.f;
        for (int t = len-2; t >= 0; t--) {
            const float x0 = em[t+1][0]+be[t+1][0];
            const float x1 = em[t+1][1]+be[t+1][1];
            be[t][0] = lse2(Ts[0]+x0, Ts[1]+x1);
            be[t][1] = lse2(Ts[2]+x0, Ts[3]+x1);
        }
    }
    __syncthreads();

    sp[tid] = (tid < len) ? __expf(al[tid][1]+be[tid][1]-logZ_s) : 0.f;
    __syncthreads();

    red[tid] = sp[tid];
    __syncthreads();
    for (int s = 128; s > 0; s >>= 1) {
        if (tid < s) red[tid] += red[tid+s];
        __syncthreads();
    }
    if (tid == 0) sumsp_s = red[0];
    __syncthreads();
    const float sum_sp = sumsp_s;

    float s1 = 0.f;
    #pragma unroll 8
    for (int l = 0; l < Ln; l++) s1 += sp[l] * hsel[l*HDn];
    const float svh = s1 + sum_sp * tv[tid];

    for (int c = 0; c < 3; c++) {
        red[tid] = svh * f2l_w[c*Hn + tid];
        __syncthreads();
        for (int s = 128; s > 0; s >>= 1) {
            if (tid < s) red[tid] += red[tid+s];
            __syncthreads();
        }
        if (tid == 0) scores[c] = red[0] + f2l_b[c];
        __syncthreads();
    }

    if (tid == 0) {
        const float m = fmaxf(scores[0], fmaxf(scores[1], scores[2]));
        const float lse = m + __logf(__expf(scores[0]-m)+__expf(scores[1]-m)+__expf(scores[2]-m));
        g_cls[b]   = lse - scores[labels[b]];
        g_spsum[b] = sum_sp;
        __threadfence();
        lastflag = (atomicAdd(&g_crf_done, 1u) == Bn-1) ? 1u : 0u;
    }
    __syncthreads();

    if (lastflag) {
        if (tid < 64) { red[tid] = g_cls[tid]; red[64+tid] = g_spsum[tid]; }
        __syncthreads();
        for (int s = 32; s > 0; s >>= 1) {
            if (tid < s) { red[tid] += red[tid+s]; red[64+tid] += red[64+tid+s]; }
            __syncthreads();
        }
        if (tid == 0) {
            const float pena = fmaxf(Ts[2]-Ts[0], 0.f) + fmaxf(Ts[1]-Ts[3], 0.f);
            out[0] = red[0] / (float)Bn;
            out[1] = 1.0f*pena + 0.1f*(red[64]/(float)Bn);
            g_crf_done = 0;   // reset for next graph replay
        }
    }
}

extern "C" void kernel_launch(void* const* d_in, const int* in_sizes, int n_in,
                              void* d_out, int out_size) {
    const int*   sents      = (const int*)d_in[0];
    const int*   masks      = (const int*)d_in[1];
    const int*   labels     = (const int*)d_in[2];
    const int*   lens       = (const int*)d_in[3];
    const float* word_embed = (const float*)d_in[4];
    const float* mask_embed = (const float*)d_in[5];
    const float* w_ih_f     = (const float*)d_in[6];
    const float* w_hh_f     = (const float*)d_in[7];
    const float* b_ih_f     = (const float*)d_in[8];
    const float* b_hh_f     = (const float*)d_in[9];
    const float* w_ih_b     = (const float*)d_in[10];
    const float* w_hh_b     = (const float*)d_in[11];
    const float* b_ih_b     = (const float*)d_in[12];
    const float* b_hh_b     = (const float*)d_in[13];
    const float* f2t_w      = (const float*)d_in[14];
    const float* f2t_b      = (const float*)d_in[15];
    const float* trans      = (const float*)d_in[16];
    const float* f2l_w      = (const float*)d_in[17];
    const float* f2l_b      = (const float*)d_in[18];
    float* out = (float*)d_out;

    cudaFuncSetAttribute(lstm_kernel,
                         cudaFuncAttributeMaxDynamicSharedMemorySize, LSTM_SMEM);
    cudaFuncSetAttribute(gemm_gates_kernel,
                         cudaFuncAttributeMaxDynamicSharedMemorySize, GEMM_SMEM);

    prep_w_kernel<<<64, 256>>>(w_hh_f, w_hh_b);                   // launch 1
    prep_ab_kernel<<<3264, 256>>>(sents, masks,                   // launch 2
                                  word_embed, mask_embed, w_ih_f, w_ih_b);
    dim3 ggrid(Bn*Ln/128, Gn/128, 2);
    gemm_gates_kernel<<<ggrid, 256, GEMM_SMEM>>>(lens,            // launch 3
                                                 b_ih_f, b_hh_f, b_ih_b, b_hh_b);
    lstm_kernel<<<2*Bn, 256, LSTM_SMEM>>>(lens);                  // launch 4 (captured)
    crf_kernel<<<Bn, 256>>>(masks, lens, labels, f2t_w, f2t_b,    // launch 5
                            trans, f2l_w, f2l_b, out);
}

// round 14
// speedup vs baseline: 1.1923x; 1.0868x over previous
#include <cuda_runtime.h>
#include <cuda_bf16.h>
#include <math.h>

#define Bn 64
#define Ln 256
#define En 300
#define Mn 50
#define Dn 350
#define HDn 128
#define Gn 512   // 4*HD
#define Hn 256
#define KPAD 352
#define NEGBIG 1e30f

typedef unsigned long long ull;

// Scratch (device globals; no allocation allowed)
__device__ float g_gates_f[Bn*Ln*Gn];
__device__ float g_gates_b[Bn*Ln*Gn];
__device__ float g_hf[Bn*Ln*HDn];
__device__ float g_hb[Bn*Ln*HDn];
// GEMM bf16 hi/lo operand scratch
__device__ __nv_bfloat16 g_A_hi[(size_t)Bn*Ln*KPAD];
__device__ __nv_bfloat16 g_A_lo[(size_t)Bn*Ln*KPAD];
__device__ __nv_bfloat16 g_B_hi[2*Gn*KPAD];
__device__ __nv_bfloat16 g_B_lo[2*Gn*KPAD];
// LSTM weights, thread-mapped (256 threads, 2 gates each)
#define KRQ 24
#define KSQ 8
__device__ ulonglong2 g_wrA[2*KRQ*256];
__device__ ulonglong2 g_wrB[2*KRQ*256];
__device__ ulonglong2 g_wsA[2*KSQ*256];
__device__ ulonglong2 g_wsB[2*KSQ*256];
__device__ float g_cls[Bn];
__device__ float g_spsum[Bn];
__device__ unsigned g_crf_done;   // zero-init; self-resetting completion counter

// Fast activations: MUFU.TANH based
__device__ __forceinline__ float tanha(float x){
    float r; asm("tanh.approx.f32 %0, %1;" : "=f"(r) : "f"(x)); return r;
}
__device__ __forceinline__ float sigf(float x){
    return fmaf(tanha(0.5f*x), 0.5f, 0.5f);
}
__device__ __forceinline__ float lse2(float a, float b){
    float m = fmaxf(a,b);
    return m + __logf(__expf(a-m)+__expf(b-m));
}
__device__ __forceinline__ void ffma2(ull &d, ull a, ull b){
    asm("fma.rn.f32x2 %0, %1, %2, %0;" : "+l"(d) : "l"(a), "l"(b));
}
__device__ __forceinline__ ull addf2(ull a, ull b){
    ull r; asm("add.rn.f32x2 %0, %1, %2;" : "=l"(r) : "l"(a), "l"(b)); return r;
}
__device__ __forceinline__ ull pack2(float lo, float hi){
    ull r; asm("mov.b64 %0, {%1, %2};" : "=l"(r) : "r"(__float_as_uint(lo)), "r"(__float_as_uint(hi))); return r;
}
__device__ __forceinline__ float2 unpk(ull v){
    unsigned lo, hi; asm("mov.b64 {%0, %1}, %2;" : "=r"(lo), "=r"(hi) : "l"(v));
    return make_float2(__uint_as_float(lo), __uint_as_float(hi));
}
__device__ __forceinline__ void splitpack(float a, float b, unsigned &hw, unsigned &lw){
    __nv_bfloat16 ha = __float2bfloat16_rn(a);
    __nv_bfloat16 hb = __float2bfloat16_rn(b);
    __nv_bfloat16 la = __float2bfloat16_rn(a - __bfloat162float(ha));
    __nv_bfloat16 lb = __float2bfloat16_rn(b - __bfloat162float(hb));
    hw = ((unsigned)__bfloat16_as_ushort(hb) << 16) | (unsigned)__bfloat16_as_ushort(ha);
    lw = ((unsigned)__bfloat16_as_ushort(lb) << 16) | (unsigned)__bfloat16_as_ushort(la);
}
__device__ __forceinline__ void cpasync16(unsigned dst, const void* src){
    asm volatile("cp.async.cg.shared.global [%0], [%1], 16;" :: "r"(dst), "l"(src));
}
#define LDSM4(d0,d1,d2,d3,addr) \
    asm volatile("ldmatrix.sync.aligned.m8n8.x4.shared.b16 {%0,%1,%2,%3}, [%4];" \
        : "=r"(d0),"=r"(d1),"=r"(d2),"=r"(d3) : "r"(addr))
#define MMA_BF16(c,a,b0v,b1v) \
    asm volatile("mma.sync.aligned.m16n8k16.row.col.f32.bf16.bf16.f32 " \
        "{%0,%1,%2,%3}, {%4,%5,%6,%7}, {%8,%9}, {%0,%1,%2,%3};" \
        : "+f"(c[0]),"+f"(c[1]),"+f"(c[2]),"+f"(c[3]) \
        : "r"(a[0]),"r"(a[1]),"r"(a[2]),"r"(a[3]), "r"(b0v),"r"(b1v))

// ---------------------------------------------------------------------------
// Kernel 0: merged prep — A gather (blocks [0,2816)), B weights ([2816,2992)),
// LSTM weight repack ([2992,3056)).
// ---------------------------------------------------------------------------
#define PREP_A_BLOCKS 2816   // 64*256 rows * 44 chunks / 256
#define PREP_B_BLOCKS 176    // 2*512 rows * 44 chunks / 256
#define PREP_W_BLOCKS 64
#define PREP_BLOCKS (PREP_A_BLOCKS + PREP_B_BLOCKS + PREP_W_BLOCKS)

__global__ void __launch_bounds__(256)
prep_kernel(const int* __restrict__ sents, const int* __restrict__ masks,
            const float* __restrict__ we, const float* __restrict__ me,
            const float* __restrict__ w_ih_f, const float* __restrict__ w_ih_b,
            const float* __restrict__ w_hh_f, const float* __restrict__ w_hh_b) {
    const int bid = blockIdx.x;
    const int t = threadIdx.x;
    if (bid < PREP_A_BLOCKS) {
        const int idx = bid*256 + t;
        const int m = idx / 44;
        const int k0 = (idx % 44) * 8;
        float v[8];
        if (k0 + 7 < En) {
            const float4* p = (const float4*)(we + (size_t)__ldg(&sents[m])*En + k0);
            const float4 x0 = p[0], x1 = p[1];
            v[0]=x0.x; v[1]=x0.y; v[2]=x0.z; v[3]=x0.w;
            v[4]=x1.x; v[5]=x1.y; v[6]=x1.z; v[7]=x1.w;
        } else {
            const int s = sents[m], mk = masks[m];
            #pragma unroll
            for (int j=0;j<8;j++){
                const int k = k0+j;
                v[j] = (k < En) ? we[(size_t)s*En + k]
                     : (k < Dn) ? me[(size_t)mk*Mn + (k-En)] : 0.f;
            }
        }
        const size_t dsto = ((size_t)m*KPAD + k0)*2;
        unsigned hw[4], lw[4];
        #pragma unroll
        for (int j=0;j<4;j++) splitpack(v[2*j], v[2*j+1], hw[j], lw[j]);
        *(uint4*)((char*)g_A_hi + dsto) = make_uint4(hw[0],hw[1],hw[2],hw[3]);
        *(uint4*)((char*)g_A_lo + dsto) = make_uint4(lw[0],lw[1],lw[2],lw[3]);
    } else if (bid < PREP_A_BLOCKS + PREP_B_BLOCKS) {
        const int idx = (bid-PREP_A_BLOCKS)*256 + t;
        const int d = idx / (Gn*44);
        const int rem = idx % (Gn*44);
        const int n = rem / 44;
        const int k0 = (rem % 44) * 8;
        const float* __restrict__ W = d ? w_ih_b : w_ih_f;
        float v[8];
        #pragma unroll
        for (int j=0;j<8;j++){
            const int k = k0+j;
            v[j] = (k < Dn) ? W[(size_t)n*Dn + k] : 0.f;
        }
        const size_t dsto = (((size_t)d*Gn + n)*KPAD + k0)*2;
        unsigned hw[4], lw[4];
        #pragma unroll
        for (int j=0;j<4;j++) splitpack(v[2*j], v[2*j+1], hw[j], lw[j]);
        *(uint4*)((char*)g_B_hi + dsto) = make_uint4(hw[0],hw[1],hw[2],hw[3]);
        *(uint4*)((char*)g_B_lo + dsto) = make_uint4(lw[0],lw[1],lw[2],lw[3]);
    } else {
        const int idx = (bid - PREP_A_BLOCKS - PREP_B_BLOCKS)*256 + t; // [0,16384)
        const int d = idx >> 13;
        const int r = idx & 8191;
        const int q = r >> 8;
        const int tt = r & 255;
        const float* __restrict__ w = d ? w_hh_b : w_hh_f;
        const int e = tt >> 1, half = tt & 1;
        const int gA = half*128 + e;
        const int gB = gA + 256;
        const float4 a = *(const float4*)&w[(size_t)gA*HDn + 4*q];
        const float4 b = *(const float4*)&w[(size_t)gB*HDn + 4*q];
        ulonglong2 ua, ub;
        ua.x = pack2(a.x, a.y); ua.y = pack2(a.z, a.w);
        ub.x = pack2(b.x, b.y); ub.y = pack2(b.z, b.w);
        if (q < KRQ) {
            g_wrA[((size_t)d*KRQ + q)*256 + tt] = ua;
            g_wrB[((size_t)d*KRQ + q)*256 + tt] = ub;
        } else {
            g_wsA[((size_t)d*KSQ + (q-KRQ))*256 + tt] = ua;
            g_wsB[((size_t)d*KSQ + (q-KRQ))*256 + tt] = ub;
        }
    }
}

// ---------------------------------------------------------------------------
// Kernel 1: bf16 hi/lo tensor-core GEMM -> fp32 gates (+bias). K=352 (11 tiles).
// ---------------------------------------------------------------------------
#define NKT 11
#define GROW 80
#define GBUF (128*GROW)
#define GSM_AH 0
#define GSM_AL (2*GBUF)
#define GSM_BH (4*GBUF)
#define GSM_BL (6*GBUF)
#define GSM_BIAS (8*GBUF)
#define GEMM_SMEM (8*GBUF + 512)

__global__ void __launch_bounds__(256, 2)
gemm_gates_kernel(const int* __restrict__ lens,
                  const float* __restrict__ b_ih_f, const float* __restrict__ b_hh_f,
                  const float* __restrict__ b_ih_b, const float* __restrict__ b_hh_b) {
    extern __shared__ char gsm[];
    const int dir = blockIdx.z;
    const int bx = blockIdx.x;
    const int m0 = bx*128;
    const int n0 = blockIdx.y*128;
    if ((bx & 1)*128 >= lens[bx >> 1]) return;

    const float* __restrict__ bih = dir ? b_ih_b : b_ih_f;
    const float* __restrict__ bhh = dir ? b_hh_b : b_hh_f;
    float* __restrict__ C = dir ? g_gates_b : g_gates_f;

    const int tid = threadIdx.x;
    float* bias_s = (float*)(gsm + GSM_BIAS);
    if (tid < 128) bias_s[tid] = bih[n0+tid] + bhh[n0+tid];

    const unsigned smb = (unsigned)__cvta_generic_to_shared(gsm);

    const int cg = tid & 3, r0 = tid >> 2;
    const __nv_bfloat16* __restrict__ Ahi = g_A_hi + (size_t)m0*KPAD;
    const __nv_bfloat16* __restrict__ Alo = g_A_lo + (size_t)m0*KPAD;
    const __nv_bfloat16* __restrict__ Bhi = g_B_hi + ((size_t)dir*Gn + n0)*KPAD;
    const __nv_bfloat16* __restrict__ Blo = g_B_lo + ((size_t)dir*Gn + n0)*KPAD;

    auto issue = [&](int kt, int buf){
        const int kb = kt*32 + cg*8;
        const unsigned bufo = buf*GBUF;
        #pragma unroll
        for (int p = 0; p < 2; p++){
            const int r = r0 + p*64;
            const unsigned d0 = bufo + r*GROW + cg*16;
            const size_t so = (size_t)r*KPAD + kb;
            cpasync16(smb + GSM_AH + d0, Ahi + so);
            cpasync16(smb + GSM_AL + d0, Alo + so);
            cpasync16(smb + GSM_BH + d0, Bhi + so);
            cpasync16(smb + GSM_BL + d0, Blo + so);
        }
        asm volatile("cp.async.commit_group;");
    };

    const int lane = tid & 31, wid = tid >> 5;
    const int wm = wid >> 2, wn = wid & 3;

    float acc[4][4][4];
    #pragma unroll
    for (int i=0;i<4;i++)
        #pragma unroll
        for (int a=0;a<4;a++)
            #pragma unroll
            for (int c=0;c<4;c++) acc[i][a][c] = 0.f;

    const int a_r = lane & 15, a_k8 = lane >> 4;
    const int b_r = lane & 7, b_h = (lane >> 3) & 1, b_k8 = lane >> 4;
    const unsigned a_base = (wm*64 + a_r)*GROW + a_k8*16;
    const unsigned b_base = (wn*32 + b_h*8 + b_r)*GROW + b_k8*16;

    issue(0, 0);
    asm volatile("cp.async.wait_group 0;");
    __syncthreads();

    for (int kt = 0; kt < NKT; kt++){
        const int buf = kt & 1;
        if (kt < NKT-1) issue(kt+1, buf^1);
        const unsigned bufo = buf*GBUF;
        #pragma unroll
        for (int kk = 0; kk < 2; kk++){
            unsigned ah[4][4], al[4][4], bh[2][4], bl[2][4];
            #pragma unroll
            for (int i=0;i<4;i++){
                const unsigned aoff = bufo + a_base + i*16*GROW + kk*32;
                LDSM4(ah[i][0],ah[i][1],ah[i][2],ah[i][3], smb + GSM_AH + aoff);
                LDSM4(al[i][0],al[i][1],al[i][2],al[i][3], smb + GSM_AL + aoff);
            }
            #pragma unroll
            for (int j=0;j<2;j++){
                const unsigned boff = bufo + b_base + j*16*GROW + kk*32;
                LDSM4(bh[j][0],bh[j][1],bh[j][2],bh[j][3], smb + GSM_BH + boff);
                LDSM4(bl[j][0],bl[j][1],bl[j][2],bl[j][3], smb + GSM_BL + boff);
            }
            #pragma unroll
            for (int i=0;i<4;i++)
                #pragma unroll
                for (int a=0;a<4;a++){
                    const int j = a>>1, s = a&1;
                    MMA_BF16(acc[i][a], ah[i], bh[j][s], bh[j][2+s]);
                    MMA_BF16(acc[i][a], al[i], bh[j][s], bh[j][2+s]);
                    MMA_BF16(acc[i][a], ah[i], bl[j][s], bl[j][2+s]);
                }
        }
        if (kt < NKT-1) asm volatile("cp.async.wait_group 0;");
        __syncthreads();
    }

    const int g = lane >> 2, q = lane & 3;
    #pragma unroll
    for (int i=0;i<4;i++){
        const int m = m0 + wm*64 + i*16 + g;
        float* c0p = C + (size_t)m*Gn + n0 + wn*32;
        float* c1p = C + (size_t)(m+8)*Gn + n0 + wn*32;
        #pragma unroll
        for (int a=0;a<4;a++){
            const int nn = a*8 + 2*q;
            const float bb0 = bias_s[wn*32 + nn], bb1 = bias_s[wn*32 + nn + 1];
            *(float2*)(c0p + nn) = make_float2(acc[i][a][0] + bb0, acc[i][a][1] + bb1);
            *(float2*)(c1p + nn) = make_float2(acc[i][a][2] + bb0, acc[i][a][3] + bb1);
        }
    }
}

// ---------------------------------------------------------------------------
// Kernel 2: LSTM recurrence (R11/R13 winner, unchanged).
// ---------------------------------------------------------------------------
#define LSTM_SMEM (2*KSQ*256*16 + 2*128*4)

__global__ void __launch_bounds__(256, 1)
lstm_kernel(const int* __restrict__ lens) {
    extern __shared__ ulonglong2 smem_v[];
    ulonglong2* sA = smem_v;
    ulonglong2* sB = smem_v + KSQ*256;
    float* hs = (float*)(smem_v + 2*KSQ*256);

    const int bx  = blockIdx.x;
    const int dir = bx >> 6;
    const int row = bx & 63;
    const float* __restrict__ gates_in = dir ? g_gates_b : g_gates_f;
    float* __restrict__ h_out          = dir ? g_hb : g_hf;

    const int tid = threadIdx.x;
    const int e = tid >> 1, half = tid & 1;
    const int gA = half*128 + e;
    const int len = lens[row];

    ulonglong2 wA[KRQ], wB[KRQ];
    {
        const ulonglong2* __restrict__ grA = g_wrA + (size_t)dir*KRQ*256;
        const ulonglong2* __restrict__ grB = g_wrB + (size_t)dir*KRQ*256;
        #pragma unroll
        for (int q = 0; q < KRQ; q++) {
            wA[q] = grA[q*256 + tid];
            wB[q] = grB[q*256 + tid];
        }
    }
    {
        const ulonglong2* __restrict__ gsA = g_wsA + (size_t)dir*KSQ*256;
        const ulonglong2* __restrict__ gsB = g_wsB + (size_t)dir*KSQ*256;
        #pragma unroll
        for (int j = 0; j < KSQ; j++) {
            sA[j*256 + tid] = gsA[j*256 + tid];
            sB[j*256 + tid] = gsB[j*256 + tid];
        }
    }
    if (tid < 128) hs[tid] = 0.f;
    float c_reg = 0.f;

    float exA, exB;
    {
        const int u0 = dir ? (len-1) : 0;
        const size_t base = ((size_t)row*Ln + u0)*Gn;
        exA = gates_in[base + gA];
        exB = gates_in[base + gA + 256];
    }
    __syncthreads();

    for (int t = 0; t < len; t++) {
        const int buf = t & 1;
        const float* hcur = hs + buf*128;
        float* hnxt = hs + (buf^1)*128;

        float nA = 0.f, nB = 0.f;
        if (t+1 < len) {
            const int un = dir ? (len-2-t) : (t+1);
            const size_t b2 = ((size_t)row*Ln + un)*Gn;
            nA = gates_in[b2 + gA];
            nB = gates_in[b2 + gA + 256];
        }

        ull a0=0, a1=0, b0=0, b1=0;
        #pragma unroll
        for (int q = 0; q < KRQ; q++) {
            const ulonglong2 hv = *(const ulonglong2*)&hcur[4*q];
            ffma2(a0, wA[q].x, hv.x); ffma2(a1, wA[q].y, hv.y);
            ffma2(b0, wB[q].x, hv.x); ffma2(b1, wB[q].y, hv.y);
        }
        #pragma unroll
        for (int j = 0; j < KSQ; j++) {
            const ulonglong2 hv = *(const ulonglong2*)&hcur[4*(KRQ+j)];
            const ulonglong2 wa = sA[j*256 + tid];
            const ulonglong2 wb = sB[j*256 + tid];
            ffma2(a0, wa.x, hv.x); ffma2(a1, wa.y, hv.y);
            ffma2(b0, wb.x, hv.x); ffma2(b1, wb.y, hv.y);
        }
        const float2 fa = unpk(addf2(a0, a1));
        const float2 fb = unpk(addf2(b0, b1));
        const float gAv = fa.x + fa.y + exA;
        const float gBv = fb.x + fb.y + exB;

        const float pA = __shfl_xor_sync(0xffffffffu, gAv, 1);
        const float pB = __shfl_xor_sync(0xffffffffu, gBv, 1);
        const float gi = half ? pA : gAv;
        const float gg = half ? pB : gBv;
        const float gf = half ? gAv : pA;
        const float go = half ? gBv : pB;

        const float c = sigf(gf)*c_reg + sigf(gi)*tanha(gg);
        const float h = sigf(go)*tanha(c);
        c_reg = c;

        if (!half) {
            const int u = dir ? (len-1-t) : t;
            hnxt[e] = h;
            h_out[((size_t)row*Ln + u)*HDn + e] = h;
        }
        exA = nA; exB = nB;
        __syncthreads();
    }
}

// ---------------------------------------------------------------------------
// Kernel 3: CRF + classifier + fused finalize. Alpha/beta via PARALLEL SCANS
// over 2x2 (log,+)-semiring matrices (8 Hillis-Steele rounds each).
// ---------------------------------------------------------------------------
__global__ void __launch_bounds__(256)
crf_kernel(const int* __restrict__ masks,
           const int* __restrict__ lens,
           const int* __restrict__ labels,
           const float* __restrict__ f2t_w,
           const float* __restrict__ f2t_b,
           const float* __restrict__ trans,
           const float* __restrict__ f2l_w,
           const float* __restrict__ f2l_b,
           float* __restrict__ out) {
    const int b = blockIdx.x;
    const int tid = threadIdx.x;

    __shared__ float tv[Hn];
    __shared__ float fw[2*Hn];
    __shared__ float em[Ln][2];
    __shared__ float s00[Ln], s01[Ln], s10[Ln], s11[Ln];  // scan buffers
    __shared__ float sp[Ln];
    __shared__ float red[Hn];
    __shared__ int   msk[Ln];
    __shared__ float Ts[4];
    __shared__ float logZ_s, sumsp_s, scores[3];
    __shared__ unsigned lastflag;

    const int len = lens[b];
    msk[tid] = masks[b*Ln + tid];
    fw[tid]      = f2t_w[tid];
    fw[Hn + tid] = f2t_w[Hn + tid];
    if (tid < 4) Ts[tid] = trans[tid];
    __syncthreads();

    const float* __restrict__ hfb = g_hf + (size_t)b*Ln*HDn;
    const float* __restrict__ hbb = g_hb + (size_t)b*Ln*HDn;
    const float* __restrict__ hsel = (tid < HDn) ? (hfb + tid) : (hbb + tid - HDn);

    // tavg: skip unmasked positions
    float num = 0.f; int cnt = 0;
    for (int l = 0; l < Ln; l++) {
        const int mf = msk[l];
        if (mf) {
            num += hsel[l*HDn] * (float)mf;
            cnt += mf;
        }
    }
    tv[tid] = num / (float)cnt;
    __syncthreads();

    // emit
    {
        const int warp = tid >> 5, lane = tid & 31;
        const float b0 = f2t_b[0], b1 = f2t_b[1];
        for (int l = warp; l < len; l += 8) {
            const float* hr  = hfb + l*HDn;
            const float* hr2 = hbb + l*HDn;
            float e0 = 0.f, e1 = 0.f;
            #pragma unroll
            for (int q = 0; q < 4; q++) {
                const int hh = lane + q*32;
                const float c  = hr[hh]  + tv[hh];
                const float c2 = hr2[hh] + tv[HDn + hh];
                e0 += c*fw[hh]      + c2*fw[HDn+hh];
                e1 += c*fw[Hn+hh]   + c2*fw[Hn+HDn+hh];
            }
            #pragma unroll
            for (int off = 16; off; off >>= 1) {
                e0 += __shfl_xor_sync(0xffffffffu, e0, off);
                e1 += __shfl_xor_sync(0xffffffffu, e1, off);
            }
            if (lane == 0) { em[l][0] = e0 + b0; em[l][1] = e1 + b1; }
        }
    }
    __syncthreads();

    // ---- prefix scan: S[t] = M_1 ∘ ... ∘ M_t (S[0]=I; M_t=I for t>=len) ----
    // M_t[i][j] = T[i][j] + em[t][j]
    float p00, p01, p10, p11;
    if (tid >= 1 && tid < len) {
        const float e0 = em[tid][0], e1 = em[tid][1];
        p00 = Ts[0] + e0; p01 = Ts[1] + e1;
        p10 = Ts[2] + e0; p11 = Ts[3] + e1;
    } else {
        p00 = 0.f; p01 = -NEGBIG; p10 = -NEGBIG; p11 = 0.f;
    }
    #pragma unroll
    for (int d = 1; d < 256; d <<= 1) {
        s00[tid]=p00; s01[tid]=p01; s10[tid]=p10; s11[tid]=p11;
        __syncthreads();
        if (tid >= d) {
            const float q00=s00[tid-d], q01=s01[tid-d], q10=s10[tid-d], q11=s11[tid-d];
            const float n00 = lse2(q00+p00, q01+p10);
            const float n01 = lse2(q00+p01, q01+p11);
            const float n10 = lse2(q10+p00, q11+p10);
            const float n11 = lse2(q10+p01, q11+p11);
            p00=n00; p01=n01; p10=n10; p11=n11;
        }
        __syncthreads();
    }
    // alpha_t = alpha_0 ∘ S[t]; alpha_0 = em[0]
    const float a_t1 = lse2(em[0][0] + p01, em[0][1] + p11);
    if (tid == len-1) {
        const float a_t0 = lse2(em[0][0] + p00, em[0][1] + p10);
        logZ_s = lse2(a_t0, a_t1);
    }
    __syncthreads();

    // ---- suffix scan: R[t] = M_{t+1} ∘ ... ∘ M_{255} (M=I beyond len) ----
    float u00, u01, u10, u11;
    if (tid+1 < len) {
        const float e0 = em[tid+1][0], e1 = em[tid+1][1];
        u00 = Ts[0] + e0; u01 = Ts[1] + e1;
        u10 = Ts[2] + e0; u11 = Ts[3] + e1;
    } else {
        u00 = 0.f; u01 = -NEGBIG; u10 = -NEGBIG; u11 = 0.f;
    }
    #pragma unroll
    for (int d = 1; d < 256; d <<= 1) {
        s00[tid]=u00; s01[tid]=u01; s10[tid]=u10; s11[tid]=u11;
        __syncthreads();
        if (tid + d < 256) {
            const float q00=s00[tid+d], q01=s01[tid+d], q10=s10[tid+d], q11=s11[tid+d];
            const float n00 = lse2(u00+q00, u01+q10);
            const float n01 = lse2(u00+q01, u01+q11);
            const float n10 = lse2(u10+q00, u11+q10);
            const float n11 = lse2(u10+q01, u11+q11);
            u00=n00; u01=n01; u10=n10; u11=n11;
        }
        __syncthreads();
    }
    const float b_t1 = lse2(u10, u11);   // beta_t[1] = lse_j R[1][j]

    sp[tid] = (tid < len) ? __expf(a_t1 + b_t1 - logZ_s) : 0.f;
    __syncthreads();

    red[tid] = sp[tid];
    __syncthreads();
    for (int s = 128; s > 0; s >>= 1) {
        if (tid < s) red[tid] += red[tid+s];
        __syncthreads();
    }
    if (tid == 0) sumsp_s = red[0];
    __syncthreads();
    const float sum_sp = sumsp_s;

    float s1 = 0.f;
    #pragma unroll 8
    for (int l = 0; l < Ln; l++) s1 += sp[l] * hsel[l*HDn];
    const float svh = s1 + sum_sp * tv[tid];

    for (int c = 0; c < 3; c++) {
        red[tid] = svh * f2l_w[c*Hn + tid];
        __syncthreads();
        for (int s = 128; s > 0; s >>= 1) {
            if (tid < s) red[tid] += red[tid+s];
            __syncthreads();
        }
        if (tid == 0) scores[c] = red[0] + f2l_b[c];
        __syncthreads();
    }

    if (tid == 0) {
        const float m = fmaxf(scores[0], fmaxf(scores[1], scores[2]));
        const float lse = m + __logf(__expf(scores[0]-m)+__expf(scores[1]-m)+__expf(scores[2]-m));
        g_cls[b]   = lse - scores[labels[b]];
        g_spsum[b] = sum_sp;
        __threadfence();
        lastflag = (atomicAdd(&g_crf_done, 1u) == Bn-1) ? 1u : 0u;
    }
    __syncthreads();

    if (lastflag) {
        if (tid < 64) { red[tid] = g_cls[tid]; red[64+tid] = g_spsum[tid]; }
        __syncthreads();
        for (int s = 32; s > 0; s >>= 1) {
            if (tid < s) { red[tid] += red[tid+s]; red[64+tid] += red[64+tid+s]; }
            __syncthreads();
        }
        if (tid == 0) {
            const float pena = fmaxf(Ts[2]-Ts[0], 0.f) + fmaxf(Ts[1]-Ts[3], 0.f);
            out[0] = red[0] / (float)Bn;
            out[1] = 1.0f*pena + 0.1f*(red[64]/(float)Bn);
            g_crf_done = 0;   // reset for next graph replay
        }
    }
}

extern "C" void kernel_launch(void* const* d_in, const int* in_sizes, int n_in,
                              void* d_out, int out_size) {
    const int*   sents      = (const int*)d_in[0];
    const int*   masks      = (const int*)d_in[1];
    const int*   labels     = (const int*)d_in[2];
    const int*   lens       = (const int*)d_in[3];
    const float* word_embed = (const float*)d_in[4];
    const float* mask_embed = (const float*)d_in[5];
    const float* w_ih_f     = (const float*)d_in[6];
    const float* w_hh_f     = (const float*)d_in[7];
    const float* b_ih_f     = (const float*)d_in[8];
    const float* b_hh_f     = (const float*)d_in[9];
    const float* w_ih_b     = (const float*)d_in[10];
    const float* w_hh_b     = (const float*)d_in[11];
    const float* b_ih_b     = (const float*)d_in[12];
    const float* b_hh_b     = (const float*)d_in[13];
    const float* f2t_w      = (const float*)d_in[14];
    const float* f2t_b      = (const float*)d_in[15];
    const float* trans      = (const float*)d_in[16];
    const float* f2l_w      = (const float*)d_in[17];
    const float* f2l_b      = (const float*)d_in[18];
    float* out = (float*)d_out;

    cudaFuncSetAttribute(lstm_kernel,
                         cudaFuncAttributeMaxDynamicSharedMemorySize, LSTM_SMEM);
    cudaFuncSetAttribute(gemm_gates_kernel,
                         cudaFuncAttributeMaxDynamicSharedMemorySize, GEMM_SMEM);

    prep_kernel<<<PREP_BLOCKS, 256>>>(sents, masks,               // launch 1
                                      word_embed, mask_embed,
                                      w_ih_f, w_ih_b, w_hh_f, w_hh_b);
    dim3 ggrid(Bn*Ln/128, Gn/128, 2);
    gemm_gates_kernel<<<ggrid, 256, GEMM_SMEM>>>(lens,            // launch 2
                                                 b_ih_f, b_hh_f, b_ih_b, b_hh_b);
    lstm_kernel<<<2*Bn, 256, LSTM_SMEM>>>(lens);                  // launch 3
    crf_kernel<<<Bn, 256>>>(masks, lens, labels, f2t_w, f2t_b,    // launch 4 (captured)
                            trans, f2l_w, f2l_b, out);
}

// round 15
// speedup vs baseline: 1.2388x; 1.0390x over previous
#include <cuda_runtime.h>
#include <cuda_bf16.h>
#include <math.h>

#define Bn 64
#define Ln 256
#define En 300
#define Mn 50
#define Dn 350
#define HDn 128
#define Gn 512   // 4*HD
#define Hn 256
#define KPAD 352
#define NEGBIG 1e30f

typedef unsigned long long ull;

// Scratch (device globals; no allocation allowed)
__device__ float g_gates_f[Bn*Ln*Gn];
__device__ float g_gates_b[Bn*Ln*Gn];
__device__ float g_hf[Bn*Ln*HDn];
__device__ float g_hb[Bn*Ln*HDn];
// GEMM bf16 hi/lo operand scratch
__device__ __nv_bfloat16 g_A_hi[(size_t)Bn*Ln*KPAD];
__device__ __nv_bfloat16 g_A_lo[(size_t)Bn*Ln*KPAD];
__device__ __nv_bfloat16 g_B_hi[2*Gn*KPAD];
__device__ __nv_bfloat16 g_B_lo[2*Gn*KPAD];
// LSTM weights, thread-mapped (256 threads, 2 gates each)
#define KRQ 24
#define KSQ 8
__device__ ulonglong2 g_wrA[2*KRQ*256];
__device__ ulonglong2 g_wrB[2*KRQ*256];
__device__ ulonglong2 g_wsA[2*KSQ*256];
__device__ ulonglong2 g_wsB[2*KSQ*256];
__device__ float g_cls[Bn];
__device__ float g_spsum[Bn];
__device__ unsigned g_crf_done;   // zero-init; self-resetting completion counter

// Fast activations: MUFU.TANH based
__device__ __forceinline__ float tanha(float x){
    float r; asm("tanh.approx.f32 %0, %1;" : "=f"(r) : "f"(x)); return r;
}
__device__ __forceinline__ float sigf(float x){
    return fmaf(tanha(0.5f*x), 0.5f, 0.5f);
}
__device__ __forceinline__ float lse2(float a, float b){
    float m = fmaxf(a,b);
    return m + __logf(__expf(a-m)+__expf(b-m));
}
__device__ __forceinline__ void ffma2(ull &d, ull a, ull b){
    asm("fma.rn.f32x2 %0, %1, %2, %0;" : "+l"(d) : "l"(a), "l"(b));
}
__device__ __forceinline__ ull addf2(ull a, ull b){
    ull r; asm("add.rn.f32x2 %0, %1, %2;" : "=l"(r) : "l"(a), "l"(b)); return r;
}
__device__ __forceinline__ ull pack2(float lo, float hi){
    ull r; asm("mov.b64 %0, {%1, %2};" : "=l"(r) : "r"(__float_as_uint(lo)), "r"(__float_as_uint(hi))); return r;
}
__device__ __forceinline__ float2 unpk(ull v){
    unsigned lo, hi; asm("mov.b64 {%0, %1}, %2;" : "=r"(lo), "=r"(hi) : "l"(v));
    return make_float2(__uint_as_float(lo), __uint_as_float(hi));
}
__device__ __forceinline__ void splitpack(float a, float b, unsigned &hw, unsigned &lw){
    __nv_bfloat16 ha = __float2bfloat16_rn(a);
    __nv_bfloat16 hb = __float2bfloat16_rn(b);
    __nv_bfloat16 la = __float2bfloat16_rn(a - __bfloat162float(ha));
    __nv_bfloat16 lb = __float2bfloat16_rn(b - __bfloat162float(hb));
    hw = ((unsigned)__bfloat16_as_ushort(hb) << 16) | (unsigned)__bfloat16_as_ushort(ha);
    lw = ((unsigned)__bfloat16_as_ushort(lb) << 16) | (unsigned)__bfloat16_as_ushort(la);
}
__device__ __forceinline__ void cpasync16(unsigned dst, const void* src){
    asm volatile("cp.async.cg.shared.global [%0], [%1], 16;" :: "r"(dst), "l"(src));
}
#define LDSM4(d0,d1,d2,d3,addr) \
    asm volatile("ldmatrix.sync.aligned.m8n8.x4.shared.b16 {%0,%1,%2,%3}, [%4];" \
        : "=r"(d0),"=r"(d1),"=r"(d2),"=r"(d3) : "r"(addr))
#define MMA_BF16(c,a,b0v,b1v) \
    asm volatile("mma.sync.aligned.m16n8k16.row.col.f32.bf16.bf16.f32 " \
        "{%0,%1,%2,%3}, {%4,%5,%6,%7}, {%8,%9}, {%0,%1,%2,%3};" \
        : "+f"(c[0]),"+f"(c[1]),"+f"(c[2]),"+f"(c[3]) \
        : "r"(a[0]),"r"(a[1]),"r"(a[2]),"r"(a[3]), "r"(b0v),"r"(b1v))

// ---------------------------------------------------------------------------
// Kernel 0: merged prep — A gather, B weights, LSTM weight repack.
// ---------------------------------------------------------------------------
#define PREP_A_BLOCKS 2816
#define PREP_B_BLOCKS 176
#define PREP_W_BLOCKS 64
#define PREP_BLOCKS (PREP_A_BLOCKS + PREP_B_BLOCKS + PREP_W_BLOCKS)

__global__ void __launch_bounds__(256)
prep_kernel(const int* __restrict__ sents, const int* __restrict__ masks,
            const float* __restrict__ we, const float* __restrict__ me,
            const float* __restrict__ w_ih_f, const float* __restrict__ w_ih_b,
            const float* __restrict__ w_hh_f, const float* __restrict__ w_hh_b) {
    const int bid = blockIdx.x;
    const int t = threadIdx.x;
    if (bid < PREP_A_BLOCKS) {
        const int idx = bid*256 + t;
        const int m = idx / 44;
        const int k0 = (idx % 44) * 8;
        float v[8];
        if (k0 + 7 < En) {
            const float4* p = (const float4*)(we + (size_t)__ldg(&sents[m])*En + k0);
            const float4 x0 = p[0], x1 = p[1];
            v[0]=x0.x; v[1]=x0.y; v[2]=x0.z; v[3]=x0.w;
            v[4]=x1.x; v[5]=x1.y; v[6]=x1.z; v[7]=x1.w;
        } else {
            const int s = sents[m], mk = masks[m];
            #pragma unroll
            for (int j=0;j<8;j++){
                const int k = k0+j;
                v[j] = (k < En) ? we[(size_t)s*En + k]
                     : (k < Dn) ? me[(size_t)mk*Mn + (k-En)] : 0.f;
            }
        }
        const size_t dsto = ((size_t)m*KPAD + k0)*2;
        unsigned hw[4], lw[4];
        #pragma unroll
        for (int j=0;j<4;j++) splitpack(v[2*j], v[2*j+1], hw[j], lw[j]);
        *(uint4*)((char*)g_A_hi + dsto) = make_uint4(hw[0],hw[1],hw[2],hw[3]);
        *(uint4*)((char*)g_A_lo + dsto) = make_uint4(lw[0],lw[1],lw[2],lw[3]);
    } else if (bid < PREP_A_BLOCKS + PREP_B_BLOCKS) {
        const int idx = (bid-PREP_A_BLOCKS)*256 + t;
        const int d = idx / (Gn*44);
        const int rem = idx % (Gn*44);
        const int n = rem / 44;
        const int k0 = (rem % 44) * 8;
        const float* __restrict__ W = d ? w_ih_b : w_ih_f;
        float v[8];
        #pragma unroll
        for (int j=0;j<8;j++){
            const int k = k0+j;
            v[j] = (k < Dn) ? W[(size_t)n*Dn + k] : 0.f;
        }
        const size_t dsto = (((size_t)d*Gn + n)*KPAD + k0)*2;
        unsigned hw[4], lw[4];
        #pragma unroll
        for (int j=0;j<4;j++) splitpack(v[2*j], v[2*j+1], hw[j], lw[j]);
        *(uint4*)((char*)g_B_hi + dsto) = make_uint4(hw[0],hw[1],hw[2],hw[3]);
        *(uint4*)((char*)g_B_lo + dsto) = make_uint4(lw[0],lw[1],lw[2],lw[3]);
    } else {
        const int idx = (bid - PREP_A_BLOCKS - PREP_B_BLOCKS)*256 + t;
        const int d = idx >> 13;
        const int r = idx & 8191;
        const int q = r >> 8;
        const int tt = r & 255;
        const float* __restrict__ w = d ? w_hh_b : w_hh_f;
        const int e = tt >> 1, half = tt & 1;
        const int gA = half*128 + e;
        const int gB = gA + 256;
        const float4 a = *(const float4*)&w[(size_t)gA*HDn + 4*q];
        const float4 b = *(const float4*)&w[(size_t)gB*HDn + 4*q];
        ulonglong2 ua, ub;
        ua.x = pack2(a.x, a.y); ua.y = pack2(a.z, a.w);
        ub.x = pack2(b.x, b.y); ub.y = pack2(b.z, b.w);
        if (q < KRQ) {
            g_wrA[((size_t)d*KRQ + q)*256 + tt] = ua;
            g_wrB[((size_t)d*KRQ + q)*256 + tt] = ub;
        } else {
            g_wsA[((size_t)d*KSQ + (q-KRQ))*256 + tt] = ua;
            g_wsB[((size_t)d*KSQ + (q-KRQ))*256 + tt] = ub;
        }
    }
}

// ---------------------------------------------------------------------------
// Kernel 1: bf16 hi/lo tensor-core GEMM -> fp32 gates (+bias). K=352 (11 tiles).
// ---------------------------------------------------------------------------
#define NKT 11
#define GROW 80
#define GBUF (128*GROW)
#define GSM_AH 0
#define GSM_AL (2*GBUF)
#define GSM_BH (4*GBUF)
#define GSM_BL (6*GBUF)
#define GSM_BIAS (8*GBUF)
#define GEMM_SMEM (8*GBUF + 512)

__global__ void __launch_bounds__(256, 2)
gemm_gates_kernel(const int* __restrict__ lens,
                  const float* __restrict__ b_ih_f, const float* __restrict__ b_hh_f,
                  const float* __restrict__ b_ih_b, const float* __restrict__ b_hh_b) {
    extern __shared__ char gsm[];
    const int dir = blockIdx.z;
    const int bx = blockIdx.x;
    const int m0 = bx*128;
    const int n0 = blockIdx.y*128;
    if ((bx & 1)*128 >= lens[bx >> 1]) return;

    const float* __restrict__ bih = dir ? b_ih_b : b_ih_f;
    const float* __restrict__ bhh = dir ? b_hh_b : b_hh_f;
    float* __restrict__ C = dir ? g_gates_b : g_gates_f;

    const int tid = threadIdx.x;
    float* bias_s = (float*)(gsm + GSM_BIAS);
    if (tid < 128) bias_s[tid] = bih[n0+tid] + bhh[n0+tid];

    const unsigned smb = (unsigned)__cvta_generic_to_shared(gsm);

    const int cg = tid & 3, r0 = tid >> 2;
    const __nv_bfloat16* __restrict__ Ahi = g_A_hi + (size_t)m0*KPAD;
    const __nv_bfloat16* __restrict__ Alo = g_A_lo + (size_t)m0*KPAD;
    const __nv_bfloat16* __restrict__ Bhi = g_B_hi + ((size_t)dir*Gn + n0)*KPAD;
    const __nv_bfloat16* __restrict__ Blo = g_B_lo + ((size_t)dir*Gn + n0)*KPAD;

    auto issue = [&](int kt, int buf){
        const int kb = kt*32 + cg*8;
        const unsigned bufo = buf*GBUF;
        #pragma unroll
        for (int p = 0; p < 2; p++){
            const int r = r0 + p*64;
            const unsigned d0 = bufo + r*GROW + cg*16;
            const size_t so = (size_t)r*KPAD + kb;
            cpasync16(smb + GSM_AH + d0, Ahi + so);
            cpasync16(smb + GSM_AL + d0, Alo + so);
            cpasync16(smb + GSM_BH + d0, Bhi + so);
            cpasync16(smb + GSM_BL + d0, Blo + so);
        }
        asm volatile("cp.async.commit_group;");
    };

    const int lane = tid & 31, wid = tid >> 5;
    const int wm = wid >> 2, wn = wid & 3;

    float acc[4][4][4];
    #pragma unroll
    for (int i=0;i<4;i++)
        #pragma unroll
        for (int a=0;a<4;a++)
            #pragma unroll
            for (int c=0;c<4;c++) acc[i][a][c] = 0.f;

    const int a_r = lane & 15, a_k8 = lane >> 4;
    const int b_r = lane & 7, b_h = (lane >> 3) & 1, b_k8 = lane >> 4;
    const unsigned a_base = (wm*64 + a_r)*GROW + a_k8*16;
    const unsigned b_base = (wn*32 + b_h*8 + b_r)*GROW + b_k8*16;

    issue(0, 0);
    asm volatile("cp.async.wait_group 0;");
    __syncthreads();

    for (int kt = 0; kt < NKT; kt++){
        const int buf = kt & 1;
        if (kt < NKT-1) issue(kt+1, buf^1);
        const unsigned bufo = buf*GBUF;
        #pragma unroll
        for (int kk = 0; kk < 2; kk++){
            unsigned ah[4][4], al[4][4], bh[2][4], bl[2][4];
            #pragma unroll
            for (int i=0;i<4;i++){
                const unsigned aoff = bufo + a_base + i*16*GROW + kk*32;
                LDSM4(ah[i][0],ah[i][1],ah[i][2],ah[i][3], smb + GSM_AH + aoff);
                LDSM4(al[i][0],al[i][1],al[i][2],al[i][3], smb + GSM_AL + aoff);
            }
            #pragma unroll
            for (int j=0;j<2;j++){
                const unsigned boff = bufo + b_base + j*16*GROW + kk*32;
                LDSM4(bh[j][0],bh[j][1],bh[j][2],bh[j][3], smb + GSM_BH + boff);
                LDSM4(bl[j][0],bl[j][1],bl[j][2],bl[j][3], smb + GSM_BL + boff);
            }
            #pragma unroll
            for (int i=0;i<4;i++)
                #pragma unroll
                for (int a=0;a<4;a++){
                    const int j = a>>1, s = a&1;
                    MMA_BF16(acc[i][a], ah[i], bh[j][s], bh[j][2+s]);
                    MMA_BF16(acc[i][a], al[i], bh[j][s], bh[j][2+s]);
                    MMA_BF16(acc[i][a], ah[i], bl[j][s], bl[j][2+s]);
                }
        }
        if (kt < NKT-1) asm volatile("cp.async.wait_group 0;");
        __syncthreads();
    }

    const int g = lane >> 2, q = lane & 3;
    #pragma unroll
    for (int i=0;i<4;i++){
        const int m = m0 + wm*64 + i*16 + g;
        float* c0p = C + (size_t)m*Gn + n0 + wn*32;
        float* c1p = C + (size_t)(m+8)*Gn + n0 + wn*32;
        #pragma unroll
        for (int a=0;a<4;a++){
            const int nn = a*8 + 2*q;
            const float bb0 = bias_s[wn*32 + nn], bb1 = bias_s[wn*32 + nn + 1];
            *(float2*)(c0p + nn) = make_float2(acc[i][a][0] + bb0, acc[i][a][1] + bb1);
            *(float2*)(c1p + nn) = make_float2(acc[i][a][2] + bb0, acc[i][a][3] + bb1);
        }
    }
}

// ---------------------------------------------------------------------------
// Kernel 2: LSTM recurrence (unchanged).
// ---------------------------------------------------------------------------
#define LSTM_SMEM (2*KSQ*256*16 + 2*128*4)

__global__ void __launch_bounds__(256, 1)
lstm_kernel(const int* __restrict__ lens) {
    extern __shared__ ulonglong2 smem_v[];
    ulonglong2* sA = smem_v;
    ulonglong2* sB = smem_v + KSQ*256;
    float* hs = (float*)(smem_v + 2*KSQ*256);

    const int bx  = blockIdx.x;
    const int dir = bx >> 6;
    const int row = bx & 63;
    const float* __restrict__ gates_in = dir ? g_gates_b : g_gates_f;
    float* __restrict__ h_out          = dir ? g_hb : g_hf;

    const int tid = threadIdx.x;
    const int e = tid >> 1, half = tid & 1;
    const int gA = half*128 + e;
    const int len = lens[row];

    ulonglong2 wA[KRQ], wB[KRQ];
    {
        const ulonglong2* __restrict__ grA = g_wrA + (size_t)dir*KRQ*256;
        const ulonglong2* __restrict__ grB = g_wrB + (size_t)dir*KRQ*256;
        #pragma unroll
        for (int q = 0; q < KRQ; q++) {
            wA[q] = grA[q*256 + tid];
            wB[q] = grB[q*256 + tid];
        }
    }
    {
        const ulonglong2* __restrict__ gsA = g_wsA + (size_t)dir*KSQ*256;
        const ulonglong2* __restrict__ gsB = g_wsB + (size_t)dir*KSQ*256;
        #pragma unroll
        for (int j = 0; j < KSQ; j++) {
            sA[j*256 + tid] = gsA[j*256 + tid];
            sB[j*256 + tid] = gsB[j*256 + tid];
        }
    }
    if (tid < 128) hs[tid] = 0.f;
    float c_reg = 0.f;

    float exA, exB;
    {
        const int u0 = dir ? (len-1) : 0;
        const size_t base = ((size_t)row*Ln + u0)*Gn;
        exA = gates_in[base + gA];
        exB = gates_in[base + gA + 256];
    }
    __syncthreads();

    for (int t = 0; t < len; t++) {
        const int buf = t & 1;
        const float* hcur = hs + buf*128;
        float* hnxt = hs + (buf^1)*128;

        float nA = 0.f, nB = 0.f;
        if (t+1 < len) {
            const int un = dir ? (len-2-t) : (t+1);
            const size_t b2 = ((size_t)row*Ln + un)*Gn;
            nA = gates_in[b2 + gA];
            nB = gates_in[b2 + gA + 256];
        }

        ull a0=0, a1=0, b0=0, b1=0;
        #pragma unroll
        for (int q = 0; q < KRQ; q++) {
            const ulonglong2 hv = *(const ulonglong2*)&hcur[4*q];
            ffma2(a0, wA[q].x, hv.x); ffma2(a1, wA[q].y, hv.y);
            ffma2(b0, wB[q].x, hv.x); ffma2(b1, wB[q].y, hv.y);
        }
        #pragma unroll
        for (int j = 0; j < KSQ; j++) {
            const ulonglong2 hv = *(const ulonglong2*)&hcur[4*(KRQ+j)];
            const ulonglong2 wa = sA[j*256 + tid];
            const ulonglong2 wb = sB[j*256 + tid];
            ffma2(a0, wa.x, hv.x); ffma2(a1, wa.y, hv.y);
            ffma2(b0, wb.x, hv.x); ffma2(b1, wb.y, hv.y);
        }
        const float2 fa = unpk(addf2(a0, a1));
        const float2 fb = unpk(addf2(b0, b1));
        const float gAv = fa.x + fa.y + exA;
        const float gBv = fb.x + fb.y + exB;

        const float pA = __shfl_xor_sync(0xffffffffu, gAv, 1);
        const float pB = __shfl_xor_sync(0xffffffffu, gBv, 1);
        const float gi = half ? pA : gAv;
        const float gg = half ? pB : gBv;
        const float gf = half ? gAv : pA;
        const float go = half ? gBv : pB;

        const float c = sigf(gf)*c_reg + sigf(gi)*tanha(gg);
        const float h = sigf(go)*tanha(c);
        c_reg = c;

        if (!half) {
            const int u = dir ? (len-1-t) : t;
            hnxt[e] = h;
            h_out[((size_t)row*Ln + u)*HDn + e] = h;
        }
        exA = nA; exB = nB;
        __syncthreads();
    }
}

// ---------------------------------------------------------------------------
// Kernel 3: CRF + classifier + fused finalize — 512 threads.
// l-loops split across two 256-thread halves; scan arrays widened to 512
// (identity beyond 256). All barriers unconditional.
// ---------------------------------------------------------------------------
__global__ void __launch_bounds__(512)
crf_kernel(const int* __restrict__ masks,
           const int* __restrict__ lens,
           const int* __restrict__ labels,
           const float* __restrict__ f2t_w,
           const float* __restrict__ f2t_b,
           const float* __restrict__ trans,
           const float* __restrict__ f2l_w,
           const float* __restrict__ f2l_b,
           float* __restrict__ out) {
    const int b = blockIdx.x;
    const int tid = threadIdx.x;     // [0,512)
    const int hh256 = tid & 255;     // h-dim
    const int lh = tid >> 8;         // l-half

    __shared__ float tv[Hn];
    __shared__ float fw[2*Hn];
    __shared__ float em[Ln][2];
    __shared__ float s00[512], s01[512], s10[512], s11[512];
    __shared__ float sp[Ln];
    __shared__ float red[Hn];
    __shared__ float pnum[512];
    __shared__ int   msk[Ln];
    __shared__ int   scnt[2];
    __shared__ float Ts[4];
    __shared__ float logZ_s, sumsp_s, scores[3];
    __shared__ unsigned lastflag;

    const int len = lens[b];
    if (tid < Ln) msk[tid] = masks[b*Ln + tid];
    fw[tid] = f2t_w[tid];            // 512 = 2*Hn values
    if (tid < 4) Ts[tid] = trans[tid];
    __syncthreads();

    const float* __restrict__ hfb = g_hf + (size_t)b*Ln*HDn;
    const float* __restrict__ hbb = g_hb + (size_t)b*Ln*HDn;
    const float* __restrict__ hsel = (hh256 < HDn) ? (hfb + hh256) : (hbb + hh256 - HDn);

    // tavg: each half covers 128 l values (skip unmasked)
    {
        float num = 0.f; int cnt = 0;
        const int lbeg = lh*128, lend = lbeg + 128;
        for (int l = lbeg; l < lend; l++) {
            const int mf = msk[l];
            if (mf) {
                num += hsel[l*HDn] * (float)mf;
                cnt += mf;
            }
        }
        pnum[tid] = num;
        if (hh256 == 0) scnt[lh] = cnt;
        __syncthreads();
        if (tid < Hn) tv[tid] = (pnum[tid] + pnum[256+tid]) / (float)(scnt[0] + scnt[1]);
        __syncthreads();
    }

    // emit: 16 warps, warp-per-position
    {
        const int warp = tid >> 5, lane = tid & 31;
        const float b0 = f2t_b[0], b1 = f2t_b[1];
        for (int l = warp; l < len; l += 16) {
            const float* hr  = hfb + l*HDn;
            const float* hr2 = hbb + l*HDn;
            float e0 = 0.f, e1 = 0.f;
            #pragma unroll
            for (int q = 0; q < 4; q++) {
                const int hq = lane + q*32;
                const float c  = hr[hq]  + tv[hq];
                const float c2 = hr2[hq] + tv[HDn + hq];
                e0 += c*fw[hq]      + c2*fw[HDn+hq];
                e1 += c*fw[Hn+hq]   + c2*fw[Hn+HDn+hq];
            }
            #pragma unroll
            for (int off = 16; off; off >>= 1) {
                e0 += __shfl_xor_sync(0xffffffffu, e0, off);
                e1 += __shfl_xor_sync(0xffffffffu, e1, off);
            }
            if (lane == 0) { em[l][0] = e0 + b0; em[l][1] = e1 + b1; }
        }
    }
    __syncthreads();

    // ---- prefix scan over 2x2 log-matrices (positions >=256 are identity) ----
    float p00, p01, p10, p11;
    if (tid >= 1 && tid < len) {
        const float e0 = em[tid][0], e1 = em[tid][1];
        p00 = Ts[0] + e0; p01 = Ts[1] + e1;
        p10 = Ts[2] + e0; p11 = Ts[3] + e1;
    } else {
        p00 = 0.f; p01 = -NEGBIG; p10 = -NEGBIG; p11 = 0.f;
    }
    #pragma unroll
    for (int d = 1; d < 256; d <<= 1) {
        s00[tid]=p00; s01[tid]=p01; s10[tid]=p10; s11[tid]=p11;
        __syncthreads();
        if (tid >= d) {
            const float q00=s00[tid-d], q01=s01[tid-d], q10=s10[tid-d], q11=s11[tid-d];
            const float n00 = lse2(q00+p00, q01+p10);
            const float n01 = lse2(q00+p01, q01+p11);
            const float n10 = lse2(q10+p00, q11+p10);
            const float n11 = lse2(q10+p01, q11+p11);
            p00=n00; p01=n01; p10=n10; p11=n11;
        }
        __syncthreads();
    }
    const float a_t1 = lse2(em[0][0] + p01, em[0][1] + p11);
    if (tid == len-1) {
        const float a_t0 = lse2(em[0][0] + p00, em[0][1] + p10);
        logZ_s = lse2(a_t0, a_t1);
    }
    __syncthreads();

    // ---- suffix scan ----
    float u00, u01, u10, u11;
    if (tid+1 < len) {
        const float e0 = em[tid+1][0], e1 = em[tid+1][1];
        u00 = Ts[0] + e0; u01 = Ts[1] + e1;
        u10 = Ts[2] + e0; u11 = Ts[3] + e1;
    } else {
        u00 = 0.f; u01 = -NEGBIG; u10 = -NEGBIG; u11 = 0.f;
    }
    #pragma unroll
    for (int d = 1; d < 256; d <<= 1) {
        s00[tid]=u00; s01[tid]=u01; s10[tid]=u10; s11[tid]=u11;
        __syncthreads();
        if (tid + d < 512) {
            const float q00=s00[tid+d], q01=s01[tid+d], q10=s10[tid+d], q11=s11[tid+d];
            const float n00 = lse2(u00+q00, u01+q10);
            const float n01 = lse2(u00+q01, u01+q11);
            const float n10 = lse2(u10+q00, u11+q10);
            const float n11 = lse2(u10+q01, u11+q11);
            u00=n00; u01=n01; u10=n10; u11=n11;
        }
        __syncthreads();
    }
    const float b_t1 = lse2(u10, u11);

    if (tid < Ln) sp[tid] = (tid < len) ? __expf(a_t1 + b_t1 - logZ_s) : 0.f;
    __syncthreads();

    // sum_sp tree reduce (256 active)
    if (tid < Hn) red[tid] = sp[tid];
    __syncthreads();
    for (int s = 128; s > 0; s >>= 1) {
        if (tid < s) red[tid] += red[tid+s];
        __syncthreads();
    }
    if (tid == 0) sumsp_s = red[0];
    __syncthreads();
    const float sum_sp = sumsp_s;

    // sent_v: each half covers 128 l values
    {
        float s1 = 0.f;
        const int lbeg = lh*128, lend = lbeg + 128;
        #pragma unroll 8
        for (int l = lbeg; l < lend; l++) s1 += sp[l] * hsel[l*HDn];
        pnum[tid] = s1;
    }
    __syncthreads();
    float svh = 0.f;
    if (tid < Hn) svh = pnum[tid] + pnum[256+tid] + sum_sp * tv[tid];

    for (int c = 0; c < 3; c++) {
        if (tid < Hn) red[tid] = svh * f2l_w[c*Hn + tid];
        __syncthreads();
        for (int s = 128; s > 0; s >>= 1) {
            if (tid < s) red[tid] += red[tid+s];
            __syncthreads();
        }
        if (tid == 0) scores[c] = red[0] + f2l_b[c];
        __syncthreads();
    }

    if (tid == 0) {
        const float m = fmaxf(scores[0], fmaxf(scores[1], scores[2]));
        const float lse = m + __logf(__expf(scores[0]-m)+__expf(scores[1]-m)+__expf(scores[2]-m));
        g_cls[b]   = lse - scores[labels[b]];
        g_spsum[b] = sum_sp;
        __threadfence();
        lastflag = (atomicAdd(&g_crf_done, 1u) == Bn-1) ? 1u : 0u;
    }
    __syncthreads();

    if (lastflag) {
        if (tid < 64) { red[tid] = g_cls[tid]; red[64+tid] = g_spsum[tid]; }
        __syncthreads();
        for (int s = 32; s > 0; s >>= 1) {
            if (tid < s) { red[tid] += red[tid+s]; red[64+tid] += red[64+tid+s]; }
            __syncthreads();
        }
        if (tid == 0) {
            const float pena = fmaxf(Ts[2]-Ts[0], 0.f) + fmaxf(Ts[1]-Ts[3], 0.f);
            out[0] = red[0] / (float)Bn;
            out[1] = 1.0f*pena + 0.1f*(red[64]/(float)Bn);
            g_crf_done = 0;   // reset for next graph replay
        }
    }
}

extern "C" void kernel_launch(void* const* d_in, const int* in_sizes, int n_in,
                              void* d_out, int out_size) {
    const int*   sents      = (const int*)d_in[0];
    const int*   masks      = (const int*)d_in[1];
    const int*   labels     = (const int*)d_in[2];
    const int*   lens       = (const int*)d_in[3];
    const float* word_embed = (const float*)d_in[4];
    const float* mask_embed = (const float*)d_in[5];
    const float* w_ih_f     = (const float*)d_in[6];
    const float* w_hh_f     = (const float*)d_in[7];
    const float* b_ih_f     = (const float*)d_in[8];
    const float* b_hh_f     = (const float*)d_in[9];
    const float* w_ih_b     = (const float*)d_in[10];
    const float* w_hh_b     = (const float*)d_in[11];
    const float* b_ih_b     = (const float*)d_in[12];
    const float* b_hh_b     = (const float*)d_in[13];
    const float* f2t_w      = (const float*)d_in[14];
    const float* f2t_b      = (const float*)d_in[15];
    const float* trans      = (const float*)d_in[16];
    const float* f2l_w      = (const float*)d_in[17];
    const float* f2l_b      = (const float*)d_in[18];
    float* out = (float*)d_out;

    cudaFuncSetAttribute(lstm_kernel,
                         cudaFuncAttributeMaxDynamicSharedMemorySize, LSTM_SMEM);
    cudaFuncSetAttribute(gemm_gates_kernel,
                         cudaFuncAttributeMaxDynamicSharedMemorySize, GEMM_SMEM);

    prep_kernel<<<PREP_BLOCKS, 256>>>(sents, masks,               // launch 1
                                      word_embed, mask_embed,
                                      w_ih_f, w_ih_b, w_hh_f, w_hh_b);
    dim3 ggrid(Bn*Ln/128, Gn/128, 2);
    gemm_gates_kernel<<<ggrid, 256, GEMM_SMEM>>>(lens,            // launch 2
                                                 b_ih_f, b_hh_f, b_ih_b, b_hh_b);
    lstm_kernel<<<2*Bn, 256, LSTM_SMEM>>>(lens);                  // launch 3
    crf_kernel<<<Bn, 512>>>(masks, lens, labels, f2t_w, f2t_b,    // launch 4 (captured)
                            trans, f2l_w, f2l_b, out);
}

// round 16
// speedup vs baseline: 1.2976x; 1.0475x over previous
#include <cuda_runtime.h>
#include <cuda_bf16.h>
#include <math.h>

#define Bn 64
#define Ln 256
#define En 300
#define Mn 50
#define Dn 350
#define HDn 128
#define Gn 512   // 4*HD
#define Hn 256
#define KPAD 352
#define NEGBIG 1e30f

typedef unsigned long long ull;

// Scratch (device globals; no allocation allowed)
__device__ float g_gates_f[Bn*Ln*Gn];
__device__ float g_gates_b[Bn*Ln*Gn];
__device__ float g_hf[Bn*Ln*HDn];
__device__ float g_hb[Bn*Ln*HDn];
// GEMM bf16 hi/lo operand scratch
__device__ __nv_bfloat16 g_A_hi[(size_t)Bn*Ln*KPAD];
__device__ __nv_bfloat16 g_A_lo[(size_t)Bn*Ln*KPAD];
__device__ __nv_bfloat16 g_B_hi[2*Gn*KPAD];
__device__ __nv_bfloat16 g_B_lo[2*Gn*KPAD];
// LSTM weights, thread-mapped (256 threads, 2 gates each)
#define KRQ 24
#define KSQ 8
__device__ ulonglong2 g_wrA[2*KRQ*256];
__device__ ulonglong2 g_wrB[2*KRQ*256];
__device__ ulonglong2 g_wsA[2*KSQ*256];
__device__ ulonglong2 g_wsB[2*KSQ*256];
__device__ float g_cls[Bn];
__device__ float g_spsum[Bn];
__device__ unsigned g_crf_done;   // zero-init; self-resetting completion counter

// Fast activations: MUFU.TANH based
__device__ __forceinline__ float tanha(float x){
    float r; asm("tanh.approx.f32 %0, %1;" : "=f"(r) : "f"(x)); return r;
}
__device__ __forceinline__ float sigf(float x){
    return fmaf(tanha(0.5f*x), 0.5f, 0.5f);
}
__device__ __forceinline__ float lse2(float a, float b){
    float m = fmaxf(a,b);
    return m + __logf(__expf(a-m)+__expf(b-m));
}
__device__ __forceinline__ void ffma2(ull &d, ull a, ull b){
    asm("fma.rn.f32x2 %0, %1, %2, %0;" : "+l"(d) : "l"(a), "l"(b));
}
__device__ __forceinline__ ull addf2(ull a, ull b){
    ull r; asm("add.rn.f32x2 %0, %1, %2;" : "=l"(r) : "l"(a), "l"(b)); return r;
}
__device__ __forceinline__ ull pack2(float lo, float hi){
    ull r; asm("mov.b64 %0, {%1, %2};" : "=l"(r) : "r"(__float_as_uint(lo)), "r"(__float_as_uint(hi))); return r;
}
__device__ __forceinline__ float2 unpk(ull v){
    unsigned lo, hi; asm("mov.b64 {%0, %1}, %2;" : "=r"(lo), "=r"(hi) : "l"(v));
    return make_float2(__uint_as_float(lo), __uint_as_float(hi));
}
__device__ __forceinline__ void splitpack(float a, float b, unsigned &hw, unsigned &lw){
    __nv_bfloat16 ha = __float2bfloat16_rn(a);
    __nv_bfloat16 hb = __float2bfloat16_rn(b);
    __nv_bfloat16 la = __float2bfloat16_rn(a - __bfloat162float(ha));
    __nv_bfloat16 lb = __float2bfloat16_rn(b - __bfloat162float(hb));
    hw = ((unsigned)__bfloat16_as_ushort(hb) << 16) | (unsigned)__bfloat16_as_ushort(ha);
    lw = ((unsigned)__bfloat16_as_ushort(lb) << 16) | (unsigned)__bfloat16_as_ushort(la);
}
__device__ __forceinline__ void cpasync16(unsigned dst, const void* src){
    asm volatile("cp.async.cg.shared.global [%0], [%1], 16;" :: "r"(dst), "l"(src));
}
#define LDSM4(d0,d1,d2,d3,addr) \
    asm volatile("ldmatrix.sync.aligned.m8n8.x4.shared.b16 {%0,%1,%2,%3}, [%4];" \
        : "=r"(d0),"=r"(d1),"=r"(d2),"=r"(d3) : "r"(addr))
#define MMA_BF16(c,a,b0v,b1v) \
    asm volatile("mma.sync.aligned.m16n8k16.row.col.f32.bf16.bf16.f32 " \
        "{%0,%1,%2,%3}, {%4,%5,%6,%7}, {%8,%9}, {%0,%1,%2,%3};" \
        : "+f"(c[0]),"+f"(c[1]),"+f"(c[2]),"+f"(c[3]) \
        : "r"(a[0]),"r"(a[1]),"r"(a[2]),"r"(a[3]), "r"(b0v),"r"(b1v))

// ---------------------------------------------------------------------------
// Kernel 0: merged prep — A gather (len-skipped), B weights, LSTM repack.
// ---------------------------------------------------------------------------
#define PREP_A_BLOCKS 2816
#define PREP_B_BLOCKS 176
#define PREP_W_BLOCKS 64
#define PREP_BLOCKS (PREP_A_BLOCKS + PREP_B_BLOCKS + PREP_W_BLOCKS)

__global__ void __launch_bounds__(256)
prep_kernel(const int* __restrict__ sents, const int* __restrict__ masks,
            const int* __restrict__ lens,
            const float* __restrict__ we, const float* __restrict__ me,
            const float* __restrict__ w_ih_f, const float* __restrict__ w_ih_b,
            const float* __restrict__ w_hh_f, const float* __restrict__ w_hh_b) {
    const int bid = blockIdx.x;
    const int t = threadIdx.x;
    if (bid < PREP_A_BLOCKS) {
        const int idx = bid*256 + t;
        const int m = idx / 44;
        const int k0 = (idx % 44) * 8;
        // skip rows never read by the 64-granular GEMM (stay zero: deterministic)
        const int l = m & 255, bb = m >> 8;
        if (l >= ((lens[bb] + 63) & ~63)) return;
        float v[8];
        if (k0 + 7 < En) {
            const float4* p = (const float4*)(we + (size_t)__ldg(&sents[m])*En + k0);
            const float4 x0 = p[0], x1 = p[1];
            v[0]=x0.x; v[1]=x0.y; v[2]=x0.z; v[3]=x0.w;
            v[4]=x1.x; v[5]=x1.y; v[6]=x1.z; v[7]=x1.w;
        } else {
            const int s = sents[m], mk = masks[m];
            #pragma unroll
            for (int j=0;j<8;j++){
                const int k = k0+j;
                v[j] = (k < En) ? we[(size_t)s*En + k]
                     : (k < Dn) ? me[(size_t)mk*Mn + (k-En)] : 0.f;
            }
        }
        const size_t dsto = ((size_t)m*KPAD + k0)*2;
        unsigned hw[4], lw[4];
        #pragma unroll
        for (int j=0;j<4;j++) splitpack(v[2*j], v[2*j+1], hw[j], lw[j]);
        *(uint4*)((char*)g_A_hi + dsto) = make_uint4(hw[0],hw[1],hw[2],hw[3]);
        *(uint4*)((char*)g_A_lo + dsto) = make_uint4(lw[0],lw[1],lw[2],lw[3]);
    } else if (bid < PREP_A_BLOCKS + PREP_B_BLOCKS) {
        const int idx = (bid-PREP_A_BLOCKS)*256 + t;
        const int d = idx / (Gn*44);
        const int rem = idx % (Gn*44);
        const int n = rem / 44;
        const int k0 = (rem % 44) * 8;
        const float* __restrict__ W = d ? w_ih_b : w_ih_f;
        float v[8];
        #pragma unroll
        for (int j=0;j<8;j++){
            const int k = k0+j;
            v[j] = (k < Dn) ? W[(size_t)n*Dn + k] : 0.f;
        }
        const size_t dsto = (((size_t)d*Gn + n)*KPAD + k0)*2;
        unsigned hw[4], lw[4];
        #pragma unroll
        for (int j=0;j<4;j++) splitpack(v[2*j], v[2*j+1], hw[j], lw[j]);
        *(uint4*)((char*)g_B_hi + dsto) = make_uint4(hw[0],hw[1],hw[2],hw[3]);
        *(uint4*)((char*)g_B_lo + dsto) = make_uint4(lw[0],lw[1],lw[2],lw[3]);
    } else {
        const int idx = (bid - PREP_A_BLOCKS - PREP_B_BLOCKS)*256 + t;
        const int d = idx >> 13;
        const int r = idx & 8191;
        const int q = r >> 8;
        const int tt = r & 255;
        const float* __restrict__ w = d ? w_hh_b : w_hh_f;
        const int e = tt >> 1, half = tt & 1;
        const int gA = half*128 + e;
        const int gB = gA + 256;
        const float4 a = *(const float4*)&w[(size_t)gA*HDn + 4*q];
        const float4 b = *(const float4*)&w[(size_t)gB*HDn + 4*q];
        ulonglong2 ua, ub;
        ua.x = pack2(a.x, a.y); ua.y = pack2(a.z, a.w);
        ub.x = pack2(b.x, b.y); ub.y = pack2(b.z, b.w);
        if (q < KRQ) {
            g_wrA[((size_t)d*KRQ + q)*256 + tt] = ua;
            g_wrB[((size_t)d*KRQ + q)*256 + tt] = ub;
        } else {
            g_wsA[((size_t)d*KSQ + (q-KRQ))*256 + tt] = ua;
            g_wsB[((size_t)d*KSQ + (q-KRQ))*256 + tt] = ub;
        }
    }
}

// ---------------------------------------------------------------------------
// Kernel 1: bf16 hi/lo tensor-core GEMM -> fp32 gates (+bias).
// 64x128 m-tiles (finer len skip), BK=32, K=352 (11 tiles), 2 CTAs/SM.
// ---------------------------------------------------------------------------
#define NKT 11
#define GROW 80
#define ABUF (64*GROW)     // 5120
#define BBUF (128*GROW)    // 10240
#define GSM_AH 0
#define GSM_AL (2*ABUF)
#define GSM_BH (4*ABUF)
#define GSM_BL (4*ABUF + 2*BBUF)
#define GSM_BIAS (4*ABUF + 4*BBUF)
#define GEMM_SMEM (4*ABUF + 4*BBUF + 512)

__global__ void __launch_bounds__(256, 2)
gemm_gates_kernel(const int* __restrict__ lens,
                  const float* __restrict__ b_ih_f, const float* __restrict__ b_hh_f,
                  const float* __restrict__ b_ih_b, const float* __restrict__ b_hh_b) {
    extern __shared__ char gsm[];
    const int dir = blockIdx.z;
    const int bx = blockIdx.x;           // 256 m-tiles of 64
    const int m0 = bx*64;
    const int n0 = blockIdx.y*128;
    if ((bx & 3)*64 >= lens[bx >> 2]) return;

    const float* __restrict__ bih = dir ? b_ih_b : b_ih_f;
    const float* __restrict__ bhh = dir ? b_hh_b : b_hh_f;
    float* __restrict__ C = dir ? g_gates_b : g_gates_f;

    const int tid = threadIdx.x;
    float* bias_s = (float*)(gsm + GSM_BIAS);
    if (tid < 128) bias_s[tid] = bih[n0+tid] + bhh[n0+tid];

    const unsigned smb = (unsigned)__cvta_generic_to_shared(gsm);

    const int cg = tid & 3, r0 = tid >> 2;
    const __nv_bfloat16* __restrict__ Ahi = g_A_hi + (size_t)m0*KPAD;
    const __nv_bfloat16* __restrict__ Alo = g_A_lo + (size_t)m0*KPAD;
    const __nv_bfloat16* __restrict__ Bhi = g_B_hi + ((size_t)dir*Gn + n0)*KPAD;
    const __nv_bfloat16* __restrict__ Blo = g_B_lo + ((size_t)dir*Gn + n0)*KPAD;

    auto issue = [&](int kt, int buf){
        const int kb = kt*32 + cg*8;
        // A: 64 rows, 1 chunk per thread per region
        {
            const unsigned d0 = buf*ABUF + r0*GROW + cg*16;
            const size_t so = (size_t)r0*KPAD + kb;
            cpasync16(smb + GSM_AH + d0, Ahi + so);
            cpasync16(smb + GSM_AL + d0, Alo + so);
        }
        // B: 128 rows, 2 chunks per thread per region
        #pragma unroll
        for (int p = 0; p < 2; p++){
            const int r = r0 + p*64;
            const unsigned d0 = buf*BBUF + r*GROW + cg*16;
            const size_t so = (size_t)r*KPAD + kb;
            cpasync16(smb + GSM_BH + d0, Bhi + so);
            cpasync16(smb + GSM_BL + d0, Blo + so);
        }
        asm volatile("cp.async.commit_group;");
    };

    const int lane = tid & 31, wid = tid >> 5;
    const int wm = wid >> 2, wn = wid & 3;

    float acc[2][4][4];
    #pragma unroll
    for (int i=0;i<2;i++)
        #pragma unroll
        for (int a=0;a<4;a++)
            #pragma unroll
            for (int c=0;c<4;c++) acc[i][a][c] = 0.f;

    const int a_r = lane & 15, a_k8 = lane >> 4;
    const int b_r = lane & 7, b_h = (lane >> 3) & 1, b_k8 = lane >> 4;
    const unsigned a_base = (wm*32 + a_r)*GROW + a_k8*16;
    const unsigned b_base = (wn*32 + b_h*8 + b_r)*GROW + b_k8*16;

    issue(0, 0);
    asm volatile("cp.async.wait_group 0;");
    __syncthreads();

    for (int kt = 0; kt < NKT; kt++){
        const int buf = kt & 1;
        if (kt < NKT-1) issue(kt+1, buf^1);
        const unsigned abufo = buf*ABUF;
        const unsigned bbufo = buf*BBUF;
        #pragma unroll
        for (int kk = 0; kk < 2; kk++){
            unsigned ah[2][4], al[2][4], bh[2][4], bl[2][4];
            #pragma unroll
            for (int i=0;i<2;i++){
                const unsigned aoff = abufo + a_base + i*16*GROW + kk*32;
                LDSM4(ah[i][0],ah[i][1],ah[i][2],ah[i][3], smb + GSM_AH + aoff);
                LDSM4(al[i][0],al[i][1],al[i][2],al[i][3], smb + GSM_AL + aoff);
            }
            #pragma unroll
            for (int j=0;j<2;j++){
                const unsigned boff = bbufo + b_base + j*16*GROW + kk*32;
                LDSM4(bh[j][0],bh[j][1],bh[j][2],bh[j][3], smb + GSM_BH + boff);
                LDSM4(bl[j][0],bl[j][1],bl[j][2],bl[j][3], smb + GSM_BL + boff);
            }
            #pragma unroll
            for (int i=0;i<2;i++)
                #pragma unroll
                for (int a=0;a<4;a++){
                    const int j = a>>1, s = a&1;
                    MMA_BF16(acc[i][a], ah[i], bh[j][s], bh[j][2+s]);
                    MMA_BF16(acc[i][a], al[i], bh[j][s], bh[j][2+s]);
                    MMA_BF16(acc[i][a], ah[i], bl[j][s], bl[j][2+s]);
                }
        }
        if (kt < NKT-1) asm volatile("cp.async.wait_group 0;");
        __syncthreads();
    }

    const int g = lane >> 2, q = lane & 3;
    #pragma unroll
    for (int i=0;i<2;i++){
        const int m = m0 + wm*32 + i*16 + g;
        float* c0p = C + (size_t)m*Gn + n0 + wn*32;
        float* c1p = C + (size_t)(m+8)*Gn + n0 + wn*32;
        #pragma unroll
        for (int a=0;a<4;a++){
            const int nn = a*8 + 2*q;
            const float bb0 = bias_s[wn*32 + nn], bb1 = bias_s[wn*32 + nn + 1];
            *(float2*)(c0p + nn) = make_float2(acc[i][a][0] + bb0, acc[i][a][1] + bb1);
            *(float2*)(c1p + nn) = make_float2(acc[i][a][2] + bb0, acc[i][a][3] + bb1);
        }
    }
}

// ---------------------------------------------------------------------------
// Kernel 2: LSTM recurrence (unchanged — at its crossbar/serial floor).
// ---------------------------------------------------------------------------
#define LSTM_SMEM (2*KSQ*256*16 + 2*128*4)

__global__ void __launch_bounds__(256, 1)
lstm_kernel(const int* __restrict__ lens) {
    extern __shared__ ulonglong2 smem_v[];
    ulonglong2* sA = smem_v;
    ulonglong2* sB = smem_v + KSQ*256;
    float* hs = (float*)(smem_v + 2*KSQ*256);

    const int bx  = blockIdx.x;
    const int dir = bx >> 6;
    const int row = bx & 63;
    const float* __restrict__ gates_in = dir ? g_gates_b : g_gates_f;
    float* __restrict__ h_out          = dir ? g_hb : g_hf;

    const int tid = threadIdx.x;
    const int e = tid >> 1, half = tid & 1;
    const int gA = half*128 + e;
    const int len = lens[row];

    ulonglong2 wA[KRQ], wB[KRQ];
    {
        const ulonglong2* __restrict__ grA = g_wrA + (size_t)dir*KRQ*256;
        const ulonglong2* __restrict__ grB = g_wrB + (size_t)dir*KRQ*256;
        #pragma unroll
        for (int q = 0; q < KRQ; q++) {
            wA[q] = grA[q*256 + tid];
            wB[q] = grB[q*256 + tid];
        }
    }
    {
        const ulonglong2* __restrict__ gsA = g_wsA + (size_t)dir*KSQ*256;
        const ulonglong2* __restrict__ gsB = g_wsB + (size_t)dir*KSQ*256;
        #pragma unroll
        for (int j = 0; j < KSQ; j++) {
            sA[j*256 + tid] = gsA[j*256 + tid];
            sB[j*256 + tid] = gsB[j*256 + tid];
        }
    }
    if (tid < 128) hs[tid] = 0.f;
    float c_reg = 0.f;

    float exA, exB;
    {
        const int u0 = dir ? (len-1) : 0;
        const size_t base = ((size_t)row*Ln + u0)*Gn;
        exA = gates_in[base + gA];
        exB = gates_in[base + gA + 256];
    }
    __syncthreads();

    for (int t = 0; t < len; t++) {
        const int buf = t & 1;
        const float* hcur = hs + buf*128;
        float* hnxt = hs + (buf^1)*128;

        float nA = 0.f, nB = 0.f;
        if (t+1 < len) {
            const int un = dir ? (len-2-t) : (t+1);
            const size_t b2 = ((size_t)row*Ln + un)*Gn;
            nA = gates_in[b2 + gA];
            nB = gates_in[b2 + gA + 256];
        }

        ull a0=0, a1=0, b0=0, b1=0;
        #pragma unroll
        for (int q = 0; q < KRQ; q++) {
            const ulonglong2 hv = *(const ulonglong2*)&hcur[4*q];
            ffma2(a0, wA[q].x, hv.x); ffma2(a1, wA[q].y, hv.y);
            ffma2(b0, wB[q].x, hv.x); ffma2(b1, wB[q].y, hv.y);
        }
        #pragma unroll
        for (int j = 0; j < KSQ; j++) {
            const ulonglong2 hv = *(const ulonglong2*)&hcur[4*(KRQ+j)];
            const ulonglong2 wa = sA[j*256 + tid];
            const ulonglong2 wb = sB[j*256 + tid];
            ffma2(a0, wa.x, hv.x); ffma2(a1, wa.y, hv.y);
            ffma2(b0, wb.x, hv.x); ffma2(b1, wb.y, hv.y);
        }
        const float2 fa = unpk(addf2(a0, a1));
        const float2 fb = unpk(addf2(b0, b1));
        const float gAv = fa.x + fa.y + exA;
        const float gBv = fb.x + fb.y + exB;

        const float pA = __shfl_xor_sync(0xffffffffu, gAv, 1);
        const float pB = __shfl_xor_sync(0xffffffffu, gBv, 1);
        const float gi = half ? pA : gAv;
        const float gg = half ? pB : gBv;
        const float gf = half ? gAv : pA;
        const float go = half ? gBv : pB;

        const float c = sigf(gf)*c_reg + sigf(gi)*tanha(gg);
        const float h = sigf(go)*tanha(c);
        c_reg = c;

        if (!half) {
            const int u = dir ? (len-1-t) : t;
            hnxt[e] = h;
            h_out[((size_t)row*Ln + u)*HDn + e] = h;
        }
        exA = nA; exB = nB;
        __syncthreads();
    }
}

// ---------------------------------------------------------------------------
// Kernel 3: CRF + classifier + fused finalize — 1024 threads.
// l-loops split 4 ways; scan uses threads [0,512) with unconditional barriers.
// ---------------------------------------------------------------------------
__global__ void __launch_bounds__(1024)
crf_kernel(const int* __restrict__ masks,
           const int* __restrict__ lens,
           const int* __restrict__ labels,
           const float* __restrict__ f2t_w,
           const float* __restrict__ f2t_b,
           const float* __restrict__ trans,
           const float* __restrict__ f2l_w,
           const float* __restrict__ f2l_b,
           float* __restrict__ out) {
    const int b = blockIdx.x;
    const int tid = threadIdx.x;     // [0,1024)
    const int hh256 = tid & 255;     // h-dim
    const int lq = tid >> 8;         // l-quarter [0,4)

    __shared__ float tv[Hn];
    __shared__ float fw[2*Hn];
    __shared__ float em[Ln][2];
    __shared__ float s00[512], s01[512], s10[512], s11[512];
    __shared__ float sp[Ln];
    __shared__ float red[Hn];
    __shared__ float pnum[1024];
    __shared__ int   msk[Ln];
    __shared__ int   scnt[4];
    __shared__ float Ts[4];
    __shared__ float logZ_s, sumsp_s, scores[3];
    __shared__ unsigned lastflag;

    const int len = lens[b];
    if (tid < Ln) msk[tid] = masks[b*Ln + tid];
    if (tid < 2*Hn) fw[tid] = f2t_w[tid];
    if (tid < 4) Ts[tid] = trans[tid];
    __syncthreads();

    const float* __restrict__ hfb = g_hf + (size_t)b*Ln*HDn;
    const float* __restrict__ hbb = g_hb + (size_t)b*Ln*HDn;
    const float* __restrict__ hsel = (hh256 < HDn) ? (hfb + hh256) : (hbb + hh256 - HDn);

    // tavg: 4 l-quarters of 64 (skip unmasked)
    {
        float num = 0.f; int cnt = 0;
        const int lbeg = lq*64, lend = lbeg + 64;
        for (int l = lbeg; l < lend; l++) {
            const int mf = msk[l];
            if (mf) {
                num += hsel[l*HDn] * (float)mf;
                cnt += mf;
            }
        }
        pnum[tid] = num;
        if (hh256 == 0) scnt[lq] = cnt;
        __syncthreads();
        if (tid < Hn)
            tv[tid] = (pnum[tid] + pnum[256+tid] + pnum[512+tid] + pnum[768+tid])
                      / (float)(scnt[0] + scnt[1] + scnt[2] + scnt[3]);
        __syncthreads();
    }

    // emit: 32 warps, warp-per-position
    {
        const int warp = tid >> 5, lane = tid & 31;
        const float b0 = f2t_b[0], b1 = f2t_b[1];
        for (int l = warp; l < len; l += 32) {
            const float* hr  = hfb + l*HDn;
            const float* hr2 = hbb + l*HDn;
            float e0 = 0.f, e1 = 0.f;
            #pragma unroll
            for (int q = 0; q < 4; q++) {
                const int hq = lane + q*32;
                const float c  = hr[hq]  + tv[hq];
                const float c2 = hr2[hq] + tv[HDn + hq];
                e0 += c*fw[hq]      + c2*fw[HDn+hq];
                e1 += c*fw[Hn+hq]   + c2*fw[Hn+HDn+hq];
            }
            #pragma unroll
            for (int off = 16; off; off >>= 1) {
                e0 += __shfl_xor_sync(0xffffffffu, e0, off);
                e1 += __shfl_xor_sync(0xffffffffu, e1, off);
            }
            if (lane == 0) { em[l][0] = e0 + b0; em[l][1] = e1 + b1; }
        }
    }
    __syncthreads();

    // ---- prefix scan over 2x2 log-matrices (threads [0,512); id beyond len) ----
    float p00 = 0.f, p01 = -NEGBIG, p10 = -NEGBIG, p11 = 0.f;
    if (tid >= 1 && tid < len) {
        const float e0 = em[tid][0], e1 = em[tid][1];
        p00 = Ts[0] + e0; p01 = Ts[1] + e1;
        p10 = Ts[2] + e0; p11 = Ts[3] + e1;
    }
    #pragma unroll
    for (int d = 1; d < 256; d <<= 1) {
        if (tid < 512) { s00[tid]=p00; s01[tid]=p01; s10[tid]=p10; s11[tid]=p11; }
        __syncthreads();
        if (tid >= d && tid < 512) {
            const float q00=s00[tid-d], q01=s01[tid-d], q10=s10[tid-d], q11=s11[tid-d];
            const float n00 = lse2(q00+p00, q01+p10);
            const float n01 = lse2(q00+p01, q01+p11);
            const float n10 = lse2(q10+p00, q11+p10);
            const float n11 = lse2(q10+p01, q11+p11);
            p00=n00; p01=n01; p10=n10; p11=n11;
        }
        __syncthreads();
    }
    const float a_t1 = lse2(em[0][0] + p01, em[0][1] + p11);
    if (tid == len-1) {
        const float a_t0 = lse2(em[0][0] + p00, em[0][1] + p10);
        logZ_s = lse2(a_t0, a_t1);
    }
    __syncthreads();

    // ---- suffix scan ----
    float u00 = 0.f, u01 = -NEGBIG, u10 = -NEGBIG, u11 = 0.f;
    if (tid+1 < len) {
        const float e0 = em[tid+1][0], e1 = em[tid+1][1];
        u00 = Ts[0] + e0; u01 = Ts[1] + e1;
        u10 = Ts[2] + e0; u11 = Ts[3] + e1;
    }
    #pragma unroll
    for (int d = 1; d < 256; d <<= 1) {
        if (tid < 512) { s00[tid]=u00; s01[tid]=u01; s10[tid]=u10; s11[tid]=u11; }
        __syncthreads();
        if (tid + d < 512) {
            const float q00=s00[tid+d], q01=s01[tid+d], q10=s10[tid+d], q11=s11[tid+d];
            const float n00 = lse2(u00+q00, u01+q10);
            const float n01 = lse2(u00+q01, u01+q11);
            const float n10 = lse2(u10+q00, u11+q10);
            const float n11 = lse2(u10+q01, u11+q11);
            u00=n00; u01=n01; u10=n10; u11=n11;
        }
        __syncthreads();
    }
    const float b_t1 = lse2(u10, u11);

    if (tid < Ln) sp[tid] = (tid < len) ? __expf(a_t1 + b_t1 - logZ_s) : 0.f;
    __syncthreads();

    // sum_sp tree reduce
    if (tid < Hn) red[tid] = sp[tid];
    __syncthreads();
    for (int s = 128; s > 0; s >>= 1) {
        if (tid < s) red[tid] += red[tid+s];
        __syncthreads();
    }
    if (tid == 0) sumsp_s = red[0];
    __syncthreads();
    const float sum_sp = sumsp_s;

    // sent_v: 4 l-quarters
    {
        float s1 = 0.f;
        const int lbeg = lq*64, lend = lbeg + 64;
        #pragma unroll 8
        for (int l = lbeg; l < lend; l++) s1 += sp[l] * hsel[l*HDn];
        pnum[tid] = s1;
    }
    __syncthreads();
    float svh = 0.f;
    if (tid < Hn)
        svh = pnum[tid] + pnum[256+tid] + pnum[512+tid] + pnum[768+tid] + sum_sp * tv[tid];

    for (int c = 0; c < 3; c++) {
        if (tid < Hn) red[tid] = svh * f2l_w[c*Hn + tid];
        __syncthreads();
        for (int s = 128; s > 0; s >>= 1) {
            if (tid < s) red[tid] += red[tid+s];
            __syncthreads();
        }
        if (tid == 0) scores[c] = red[0] + f2l_b[c];
        __syncthreads();
    }

    if (tid == 0) {
        const float m = fmaxf(scores[0], fmaxf(scores[1], scores[2]));
        const float lse = m + __logf(__expf(scores[0]-m)+__expf(scores[1]-m)+__expf(scores[2]-m));
        g_cls[b]   = lse - scores[labels[b]];
        g_spsum[b] = sum_sp;
        __threadfence();
        lastflag = (atomicAdd(&g_crf_done, 1u) == Bn-1) ? 1u : 0u;
    }
    __syncthreads();

    if (lastflag) {
        if (tid < 64) { red[tid] = g_cls[tid]; red[64+tid] = g_spsum[tid]; }
        __syncthreads();
        for (int s = 32; s > 0; s >>= 1) {
            if (tid < s) { red[tid] += red[tid+s]; red[64+tid] += red[64+tid+s]; }
            __syncthreads();
        }
        if (tid == 0) {
            const float pena = fmaxf(Ts[2]-Ts[0], 0.f) + fmaxf(Ts[1]-Ts[3], 0.f);
            out[0] = red[0] / (float)Bn;
            out[1] = 1.0f*pena + 0.1f*(red[64]/(float)Bn);
            g_crf_done = 0;   // reset for next graph replay
        }
    }
}

extern "C" void kernel_launch(void* const* d_in, const int* in_sizes, int n_in,
                              void* d_out, int out_size) {
    const int*   sents      = (const int*)d_in[0];
    const int*   masks      = (const int*)d_in[1];
    const int*   labels     = (const int*)d_in[2];
    const int*   lens       = (const int*)d_in[3];
    const float* word_embed = (const float*)d_in[4];
    const float* mask_embed = (const float*)d_in[5];
    const float* w_ih_f     = (const float*)d_in[6];
    const float* w_hh_f     = (const float*)d_in[7];
    const float* b_ih_f     = (const float*)d_in[8];
    const float* b_hh_f     = (const float*)d_in[9];
    const float* w_ih_b     = (const float*)d_in[10];
    const float* w_hh_b     = (const float*)d_in[11];
    const float* b_ih_b     = (const float*)d_in[12];
    const float* b_hh_b     = (const float*)d_in[13];
    const float* f2t_w      = (const float*)d_in[14];
    const float* f2t_b      = (const float*)d_in[15];
    const float* trans      = (const float*)d_in[16];
    const float* f2l_w      = (const float*)d_in[17];
    const float* f2l_b      = (const float*)d_in[18];
    float* out = (float*)d_out;

    cudaFuncSetAttribute(lstm_kernel,
                         cudaFuncAttributeMaxDynamicSharedMemorySize, LSTM_SMEM);
    cudaFuncSetAttribute(gemm_gates_kernel,
                         cudaFuncAttributeMaxDynamicSharedMemorySize, GEMM_SMEM);

    prep_kernel<<<PREP_BLOCKS, 256>>>(sents, masks, lens,         // launch 1
                                      word_embed, mask_embed,
                                      w_ih_f, w_ih_b, w_hh_f, w_hh_b);
    dim3 ggrid(Bn*Ln/64, Gn/128, 2);
    gemm_gates_kernel<<<ggrid, 256, GEMM_SMEM>>>(lens,            // launch 2
                                                 b_ih_f, b_hh_f, b_ih_b, b_hh_b);
    lstm_kernel<<<2*Bn, 256, LSTM_SMEM>>>(lens);                  // launch 3
    crf_kernel<<<Bn, 1024>>>(masks, lens, labels, f2t_w, f2t_b,   // launch 4 (captured)
                             trans, f2l_w, f2l_b, out);
}